// round 9
// baseline (speedup 1.0000x reference)
#include <cuda_runtime.h>
#include <cuda_bf16.h>
#include <cstdint>

#define T_STEPS 64
#define B_ENV 128
#define L_TOK 64
#define E_DIM 256
#define H_DIM 32
#define N_TOT (T_STEPS * B_ENV)

__device__ float g_M[65536];
__device__ float g_WeffT[65536];
__device__ float g_W2[32768];
__device__ float g_bias[128];
__device__ unsigned short g_MtH[65536]; // bf16 hi of M^T [j][i]
__device__ unsigned short g_MtL[65536]; // bf16 lo
__device__ float g_xg[(size_t)N_TOT * 128];

// ---------------- helpers ----------------
__device__ __forceinline__ uint32_t smem_u32(const void* p) {
    uint32_t a;
    asm("{ .reg .u64 t; cvta.to.shared.u64 t, %1; cvt.u32.u64 %0, t; }" : "=r"(a) : "l"(p));
    return a;
}
__device__ __forceinline__ void ldm4(uint32_t* r, uint32_t a) {
    asm volatile("ldmatrix.sync.aligned.m8n8.x4.shared.b16 {%0,%1,%2,%3}, [%4];"
        : "=r"(r[0]), "=r"(r[1]), "=r"(r[2]), "=r"(r[3]) : "r"(a));
}
__device__ __forceinline__ void mma_bf16(float* d, const uint32_t* a, const uint32_t* b) {
    asm volatile("mma.sync.aligned.m16n8k16.row.col.f32.bf16.bf16.f32 "
        "{%0,%1,%2,%3}, {%4,%5,%6,%7}, {%8,%9}, {%0,%1,%2,%3};"
        : "+f"(d[0]), "+f"(d[1]), "+f"(d[2]), "+f"(d[3])
        : "r"(a[0]), "r"(a[1]), "r"(a[2]), "r"(a[3]), "r"(b[0]), "r"(b[1]));
}
__device__ __forceinline__ uint32_t pack_bf2(__nv_bfloat16 lo, __nv_bfloat16 hi) {
    __nv_bfloat162 p = __halves2bfloat162(lo, hi);
    return *(uint32_t*)&p;
}
__device__ __forceinline__ void cp16(uint32_t dst, const void* src) {
    asm volatile("cp.async.cg.shared.global [%0], [%1], 16;" :: "r"(dst), "l"(src));
}
#define CP_COMMIT() asm volatile("cp.async.commit_group;" ::: "memory")
#define CP_WAIT0()  asm volatile("cp.async.wait_group 0;" ::: "memory")

// ---------------- prep1: M (b<64), WeffT (b>=64) ----------------
__global__ void __launch_bounds__(256) prep1(const float* __restrict__ ipw, const float* __restrict__ opw) {
    __shared__ float As[32][33], Bs[32][33];
    const int b = blockIdx.x, tid = threadIdx.x, tx = tid & 31, ty = tid >> 5;
    float acc[4] = {0.f, 0.f, 0.f, 0.f};
    if (b < 64) {
        int i0 = (b >> 3) * 32, j0 = (b & 7) * 32;
        const float *Wq = ipw, *Wk = ipw + 65536;
        for (int e0 = 0; e0 < 256; e0 += 32) {
#pragma unroll
            for (int r = 0; r < 4; r++) {
                int e = ty + 8 * r;
                As[e][tx] = Wq[(e0 + e) * 256 + i0 + tx];
                Bs[e][tx] = Wk[(e0 + e) * 256 + j0 + tx];
            }
            __syncthreads();
#pragma unroll 8
            for (int e = 0; e < 32; e++) {
                float bv = Bs[e][tx];
#pragma unroll
                for (int r = 0; r < 4; r++) acc[r] += As[e][ty + 8 * r] * bv;
            }
            __syncthreads();
        }
#pragma unroll
        for (int r = 0; r < 4; r++) g_M[(i0 + ty + 8 * r) * 256 + j0 + tx] = acc[r];
    } else {
        int t = b - 64, j0 = (t >> 3) * 32, f0 = (t & 7) * 32;
        const float* Wv = ipw + 131072;
        for (int e0 = 0; e0 < 256; e0 += 32) {
#pragma unroll
            for (int r = 0; r < 4; r++) {
                int e = ty + 8 * r;
                As[e][tx] = Wv[(e0 + e) * 256 + j0 + tx];
                Bs[tx][e] = opw[(f0 + e) * 256 + e0 + tx];
            }
            __syncthreads();
#pragma unroll 8
            for (int e = 0; e < 32; e++) {
                float bv = Bs[e][tx];
#pragma unroll
                for (int r = 0; r < 4; r++) acc[r] += As[e][ty + 8 * r] * bv;
            }
            __syncthreads();
        }
#pragma unroll
        for (int r = 0; r < 4; r++) g_WeffT[(j0 + ty + 8 * r) * 256 + f0 + tx] = acc[r];
    }
}

// ---------------- prep2: Mt split (b<64), W2 (64..95), bias (96) ----------------
__global__ void __launch_bounds__(256) prep2(const float* __restrict__ wih,
                                             const float* __restrict__ bih,
                                             const float* __restrict__ bhh) {
    __shared__ float As[32][33], Bs[32][33];
    const int b = blockIdx.x, tid = threadIdx.x, tx = tid & 31, ty = tid >> 5;
    if (b < 64) {
        int i0 = (b >> 3) * 32, j0 = (b & 7) * 32;
#pragma unroll
        for (int r = 0; r < 4; r++) As[ty + 8 * r][tx] = g_M[(i0 + ty + 8 * r) * 256 + j0 + tx];
        __syncthreads();
#pragma unroll
        for (int r = 0; r < 4; r++) {
            int jj = ty + 8 * r;
            float v = As[tx][jj];
            __nv_bfloat16 h = __float2bfloat16_rn(v);
            __nv_bfloat16 l = __float2bfloat16_rn(v - __bfloat162float(h));
            g_MtH[(j0 + jj) * 256 + i0 + tx] = *(unsigned short*)&h;
            g_MtL[(j0 + jj) * 256 + i0 + tx] = *(unsigned short*)&l;
        }
        return;
    }
    if (b < 96) {
        int t = b - 64, j0 = (t >> 2) * 32, g0 = (t & 3) * 32;
        float acc[4] = {0.f, 0.f, 0.f, 0.f};
        for (int f0 = 0; f0 < 256; f0 += 32) {
#pragma unroll
            for (int r = 0; r < 4; r++) {
                int e = ty + 8 * r;
                As[tx][e] = g_WeffT[(j0 + e) * 256 + f0 + tx];
                Bs[tx][e] = wih[(g0 + e) * 256 + f0 + tx];
            }
            __syncthreads();
#pragma unroll 8
            for (int f = 0; f < 32; f++) {
                float bv = Bs[f][tx];
#pragma unroll
                for (int r = 0; r < 4; r++) acc[r] += As[f][ty + 8 * r] * bv;
            }
            __syncthreads();
        }
#pragma unroll
        for (int r = 0; r < 4; r++) g_W2[(j0 + ty + 8 * r) * 128 + g0 + tx] = acc[r];
        return;
    }
    if (tid < 128) g_bias[tid] = bih[tid] + bhh[tid];
}

// ---------------- attention: 256 thr, 8 warps, m32n32 tiles ----------------
#define XH_OFF   0        /* 2 x 64 x 512 */
#define XL_OFF   65536
#define STGH_OFF 131072   /* 64 x 512 */
#define STGL_OFF 163840
#define TSH_OFF  196608   /* 2 x 64 x 128 */
#define TSL_OFF  212992
#define SMEM_SZ  229376
#define SC_OFF   STGH_OFF          /* f32 [2][64][68] after GEMMs */
#define DF_OFF   TSH_OFF           /* overlays ts after GEMMs */
#define WGT_OFF  (TSH_OFF + 512)
#define XW_OFF   (TSH_OFF + 1024)
#define MODE_OFF (TSH_OFF + 3072)

__global__ void __launch_bounds__(256, 1) attn_mma(const float* __restrict__ x,
                                                   const void* __restrict__ mask) {
    extern __shared__ char smem[];
    const uint32_t sb = smem_u32(smem);
    const int tid = threadIdx.x, lane = tid & 31, w = tid >> 5;
    const int n0 = blockIdx.x * 2;

    // stage chunk 0 of Mt (hi+lo) via cp.async
    for (int u = tid; u < 4096; u += 256) {
        int buf = u >> 11, v = u & 2047;
        int row = v >> 5, c16 = (v & 31) << 4;
        uint32_t d = (buf ? STGL_OFF : STGH_OFF) + row * 512 + (c16 ^ ((row & 7) << 4));
        cp16(sb + d, (const uint4*)(buf ? g_MtL : g_MtH) + v);
    }
    CP_COMMIT();

    // load x (2 samples) f32 -> bf16 hi/lo smem (swizzled)
    const float2* xb = (const float2*)(x + (size_t)n0 * (L_TOK * E_DIM));
    for (int idx = tid; idx < 16384; idx += 256) {
        int s = idx >> 13, r = (idx >> 7) & 63, cp = idx & 127;
        float2 v = xb[idx];
        __nv_bfloat16 h0 = __float2bfloat16_rn(v.x), h1 = __float2bfloat16_rn(v.y);
        __nv_bfloat16 l0 = __float2bfloat16_rn(v.x - __bfloat162float(h0));
        __nv_bfloat16 l1 = __float2bfloat16_rn(v.y - __bfloat162float(h1));
        uint32_t boff = (uint32_t)(s * 32768 + r * 512 + ((cp * 4) ^ ((r & 7) << 4)));
        *(uint32_t*)(smem + XH_OFF + boff) = pack_bf2(h0, h1);
        *(uint32_t*)(smem + XL_OFF + boff) = pack_bf2(l0, l1);
    }
    CP_WAIT0();
    __syncthreads();

    // warp layout: s = w>>2 (sample), 2x2 grid of m32n32 tiles
    const int s = w >> 2, w4 = w & 3, mg = w4 >> 1, ng = w4 & 1;
    const uint32_t a_rot = (uint32_t)(lane & 7) << 4;
    const uint32_t a_klo = (uint32_t)(lane >> 4) << 4;
    const uint32_t axh = sb + XH_OFF + s * 32768 + (mg * 32 + (lane & 15)) * 512;
    const uint32_t axl = sb + XL_OFF + s * 32768 + (mg * 32 + (lane & 15)) * 512;
    const uint32_t ath = sb + TSH_OFF + s * 8192 + (mg * 32 + (lane & 15)) * 128;
    const uint32_t atl = sb + TSL_OFF + s * 8192 + (mg * 32 + (lane & 15)) * 128;
    const int br0 = ng * 32 + (lane & 7) + ((lane & 16) >> 1);   // + {0,16} row blocks
    const uint32_t b_rot = (uint32_t)(br0 & 7) << 4;
    const uint32_t bklo = (uint32_t)((lane >> 3) & 1) << 4;

    float acc2[2][4][4];
#pragma unroll
    for (int mt = 0; mt < 2; mt++)
#pragma unroll
        for (int nf = 0; nf < 4; nf++)
#pragma unroll
            for (int q = 0; q < 4; q++) acc2[mt][nf][q] = 0.f;

    for (int ch = 0; ch < 4; ch++) {
        // GEMM1 chunk: ts_ch[64][64] = x_s @ Mt_ch^T (3 terms, K=256)
        float acc1[2][4][4];
#pragma unroll
        for (int mt = 0; mt < 2; mt++)
#pragma unroll
            for (int nf = 0; nf < 4; nf++)
#pragma unroll
                for (int q = 0; q < 4; q++) acc1[mt][nf][q] = 0.f;
        const uint32_t sgh = sb + STGH_OFF + br0 * 512;
        const uint32_t sgl = sb + STGL_OFF + br0 * 512;
#pragma unroll 2
        for (int ks = 0; ks < 16; ks++) {
            uint32_t kb = ks * 32;
            uint32_t aoff = (kb + a_klo) ^ a_rot, boff = (kb + bklo) ^ b_rot;
            uint32_t Ah0[4], Ah1[4], Al0[4], Al1[4], Bh0[4], Bh1[4], Bl0[4], Bl1[4];
            ldm4(Ah0, axh + aoff); ldm4(Ah1, axh + 8192 + aoff);
            ldm4(Al0, axl + aoff); ldm4(Al1, axl + 8192 + aoff);
            ldm4(Bh0, sgh + boff); ldm4(Bh1, sgh + 8192 + boff);
            ldm4(Bl0, sgl + boff); ldm4(Bl1, sgl + 8192 + boff);
            mma_bf16(acc1[0][0], Ah0, Bh0); mma_bf16(acc1[0][1], Ah0, Bh0 + 2);
            mma_bf16(acc1[0][2], Ah0, Bh1); mma_bf16(acc1[0][3], Ah0, Bh1 + 2);
            mma_bf16(acc1[1][0], Ah1, Bh0); mma_bf16(acc1[1][1], Ah1, Bh0 + 2);
            mma_bf16(acc1[1][2], Ah1, Bh1); mma_bf16(acc1[1][3], Ah1, Bh1 + 2);
            mma_bf16(acc1[0][0], Al0, Bh0); mma_bf16(acc1[0][1], Al0, Bh0 + 2);
            mma_bf16(acc1[0][2], Al0, Bh1); mma_bf16(acc1[0][3], Al0, Bh1 + 2);
            mma_bf16(acc1[1][0], Al1, Bh0); mma_bf16(acc1[1][1], Al1, Bh0 + 2);
            mma_bf16(acc1[1][2], Al1, Bh1); mma_bf16(acc1[1][3], Al1, Bh1 + 2);
            mma_bf16(acc1[0][0], Ah0, Bl0); mma_bf16(acc1[0][1], Ah0, Bl0 + 2);
            mma_bf16(acc1[0][2], Ah0, Bl1); mma_bf16(acc1[0][3], Ah0, Bl1 + 2);
            mma_bf16(acc1[1][0], Ah1, Bl0); mma_bf16(acc1[1][1], Ah1, Bl0 + 2);
            mma_bf16(acc1[1][2], Ah1, Bl1); mma_bf16(acc1[1][3], Ah1, Bl1 + 2);
        }
        // write ts chunk (bf16 hi/lo, swizzled 128B rows)
#pragma unroll
        for (int mt = 0; mt < 2; mt++)
#pragma unroll
            for (int nf = 0; nf < 4; nf++) {
                int col = ng * 32 + nf * 8 + 2 * (lane & 3);
                int r0 = mg * 32 + mt * 16 + (lane >> 2);
#pragma unroll
                for (int hh = 0; hh < 2; hh++) {
                    int rr = r0 + 8 * hh;
                    float v0 = acc1[mt][nf][2 * hh], v1 = acc1[mt][nf][2 * hh + 1];
                    __nv_bfloat16 h0 = __float2bfloat16_rn(v0), h1 = __float2bfloat16_rn(v1);
                    __nv_bfloat16 l0 = __float2bfloat16_rn(v0 - __bfloat162float(h0));
                    __nv_bfloat16 l1 = __float2bfloat16_rn(v1 - __bfloat162float(h1));
                    uint32_t boff = (uint32_t)(s * 8192 + rr * 128 + ((col * 2) ^ ((rr & 7) << 4)));
                    *(uint32_t*)(smem + TSH_OFF + boff) = pack_bf2(h0, h1);
                    *(uint32_t*)(smem + TSL_OFF + boff) = pack_bf2(l0, l1);
                }
            }
        __syncthreads();   // ts visible; GEMM1 done reading STG

        // prefetch next Mt chunk (overlaps GEMM2)
        if (ch < 3) {
            for (int u = tid; u < 4096; u += 256) {
                int buf = u >> 11, v = u & 2047;
                int row = v >> 5, c16 = (v & 31) << 4;
                uint32_t d = (buf ? STGL_OFF : STGH_OFF) + row * 512 + (c16 ^ ((row & 7) << 4));
                cp16(sb + d, (const uint4*)((buf ? g_MtL : g_MtH) + (ch + 1) * 16384) + v);
            }
            CP_COMMIT();
        }

        // GEMM2 partial: sc_s += ts_ch @ x_ch^T (3 terms, K=64)
        const uint32_t bxh = sb + XH_OFF + s * 32768 + br0 * 512;
        const uint32_t bxl = sb + XL_OFF + s * 32768 + br0 * 512;
#pragma unroll
        for (int ks = 0; ks < 4; ks++) {
            uint32_t kb = ks * 32;
            uint32_t taoff = (kb + a_klo) ^ a_rot;
            uint32_t xoff = (uint32_t)(ch * 128 + kb + bklo) ^ b_rot;
            uint32_t Ah0[4], Ah1[4], Al0[4], Al1[4], Bh0[4], Bh1[4], Bl0[4], Bl1[4];
            ldm4(Ah0, ath + taoff); ldm4(Ah1, ath + 2048 + taoff);
            ldm4(Al0, atl + taoff); ldm4(Al1, atl + 2048 + taoff);
            ldm4(Bh0, bxh + xoff); ldm4(Bh1, bxh + 8192 + xoff);
            ldm4(Bl0, bxl + xoff); ldm4(Bl1, bxl + 8192 + xoff);
            mma_bf16(acc2[0][0], Ah0, Bh0); mma_bf16(acc2[0][1], Ah0, Bh0 + 2);
            mma_bf16(acc2[0][2], Ah0, Bh1); mma_bf16(acc2[0][3], Ah0, Bh1 + 2);
            mma_bf16(acc2[1][0], Ah1, Bh0); mma_bf16(acc2[1][1], Ah1, Bh0 + 2);
            mma_bf16(acc2[1][2], Ah1, Bh1); mma_bf16(acc2[1][3], Ah1, Bh1 + 2);
            mma_bf16(acc2[0][0], Al0, Bh0); mma_bf16(acc2[0][1], Al0, Bh0 + 2);
            mma_bf16(acc2[0][2], Al0, Bh1); mma_bf16(acc2[0][3], Al0, Bh1 + 2);
            mma_bf16(acc2[1][0], Al1, Bh0); mma_bf16(acc2[1][1], Al1, Bh0 + 2);
            mma_bf16(acc2[1][2], Al1, Bh1); mma_bf16(acc2[1][3], Al1, Bh1 + 2);
            mma_bf16(acc2[0][0], Ah0, Bl0); mma_bf16(acc2[0][1], Ah0, Bl0 + 2);
            mma_bf16(acc2[0][2], Ah0, Bl1); mma_bf16(acc2[0][3], Ah0, Bl1 + 2);
            mma_bf16(acc2[1][0], Ah1, Bl0); mma_bf16(acc2[1][1], Ah1, Bl0 + 2);
            mma_bf16(acc2[1][2], Ah1, Bl1); mma_bf16(acc2[1][3], Ah1, Bl1 + 2);
        }
        if (ch < 3) { CP_WAIT0(); }
        __syncthreads();   // next GEMM1 may read STG; ts rewrite safe
    }

    // ---- write sc (overlay STG), scaled; warp 0 detects mask dtype ----
    float* scp = (float*)(smem + SC_OFF) + s * 4352;
#pragma unroll
    for (int mt = 0; mt < 2; mt++)
#pragma unroll
        for (int nf = 0; nf < 4; nf++) {
            int col = ng * 32 + nf * 8 + 2 * (lane & 3);
            int r0 = mg * 32 + mt * 16 + (lane >> 2);
            scp[r0 * 68 + col]           = acc2[mt][nf][0] * 0.0625f;
            scp[r0 * 68 + col + 1]       = acc2[mt][nf][1] * 0.0625f;
            scp[(r0 + 8) * 68 + col]     = acc2[mt][nf][2] * 0.0625f;
            scp[(r0 + 8) * 68 + col + 1] = acc2[mt][nf][3] * 0.0625f;
        }
    if (w == 0) {
        const unsigned* mw = (const unsigned*)mask;
        int f = 0, g = 0;
        for (int i = lane; i < 2048; i += 32) {
            unsigned v = mw[i];
            f |= (v == 0x3F800000u);
            g |= (v > 1u);
        }
        f = __any_sync(0xffffffffu, f);
        g = __any_sync(0xffffffffu, g);
        if (!lane) *(int*)(smem + MODE_OFF) = f ? 2 : (g ? 1 : 0);
    }
    __syncthreads();

    // ---- dropped flags + wgt init ----
    float* dfp = (float*)(smem + DF_OFF);
    float* wgt = (float*)(smem + WGT_OFF);
    float* xw  = (float*)(smem + XW_OFF);
    if (tid < 128) {
        int mode = *(int*)(smem + MODE_OFF);
        size_t mi = (size_t)n0 * 64 + tid;
        bool at;
        if (mode == 0)      at = ((const int*)mask)[mi] != 0;
        else if (mode == 1) at = ((const uint8_t*)mask)[mi] != 0;
        else                at = ((const float*)mask)[mi] != 0.f;
        dfp[tid] = at ? 0.f : 1.f;
        wgt[tid] = 0.f;
    }
    __syncthreads();

    // ---- softmax: 16 rows/warp ----
    {
        const float* scs = (const float*)(smem + SC_OFF) + s * 4352;
        const float* dfs = dfp + s * 64;
        const bool dk0 = dfs[lane] > 0.5f, dk1 = dfs[lane + 32] > 0.5f;
        float wa0 = 0.f, wa1 = 0.f;
#pragma unroll
        for (int r = 0; r < 16; r++) {
            int lq = w4 * 16 + r;
            bool dq = dfs[lq] > 0.5f;
            float s0 = scs[lq * 68 + lane], s1 = scs[lq * 68 + lane + 32];
            if (dq && dk0) s0 = -1e30f;
            if (dq && dk1) s1 = -1e30f;
            float m = fmaxf(s0, s1);
#pragma unroll
            for (int o = 16; o; o >>= 1) m = fmaxf(m, __shfl_xor_sync(0xffffffffu, m, o));
            float e0 = __expf(s0 - m), e1 = __expf(s1 - m);
            float ss = e0 + e1;
#pragma unroll
            for (int o = 16; o; o >>= 1) ss += __shfl_xor_sync(0xffffffffu, ss, o);
            float inv = 1.f / ss;
            wa0 += e0 * inv;
            wa1 += e1 * inv;
        }
        atomicAdd(&wgt[s * 64 + lane], wa0);
        atomicAdd(&wgt[s * 64 + lane + 32], wa1);
    }
    __syncthreads();

    // ---- xw[ss][j] = sum_k wgt[ss][k] * x[ss][k][j] (hi+lo, swizzled) ----
#pragma unroll
    for (int ss = 0; ss < 2; ss++) {
        float a = 0.f;
#pragma unroll 8
        for (int k = 0; k < 64; k++) {
            uint32_t boff = (uint32_t)(ss * 32768 + k * 512 + ((2 * tid) ^ ((k & 7) << 4)));
            a += wgt[ss * 64 + k] *
                 (__bfloat162float(*(__nv_bfloat16*)(smem + XH_OFF + boff)) +
                  __bfloat162float(*(__nv_bfloat16*)(smem + XL_OFF + boff)));
        }
        xw[ss * 256 + tid] = a;
    }
    __syncthreads();

    // ---- xg[ss][g] = bias[g] + sum_j xw[ss][j] * W2[j][g] ----
    {
        const int ss = tid >> 7, g = tid & 127;
        float a = g_bias[g];
        const float* xwp = xw + ss * 256;
        const float* Wp = g_W2 + g;
#pragma unroll 4
        for (int j = 0; j < 256; j++) a += xwp[j] * __ldg(Wp + (size_t)j * 128);
        g_xg[(size_t)(n0 + ss) * 128 + g] = a;
    }
}

// ---------------- LSTM scan + critic (pipelined, 32 blocks x 4 warps) --------
__device__ __forceinline__ float sigmoidf_(float v) { return 1.f / (1.f + __expf(-v)); }

__global__ void __launch_bounds__(128) lstm_kernel(const float* __restrict__ done,
                                                   const float* __restrict__ h0,
                                                   const float* __restrict__ c0,
                                                   const float* __restrict__ whh,
                                                   const float* __restrict__ cw,
                                                   const float* __restrict__ cb,
                                                   float* __restrict__ out) {
    __shared__ float whs[32 * 128];
    const int tid = threadIdx.x, lane = tid & 31, w = tid >> 5;
    const int b = blockIdx.x * 4 + w;
    for (int idx = tid; idx < 4096; idx += 128) {
        int g = idx >> 5, m = idx & 31;
        whs[m * 128 + g] = whh[idx];
    }
    __syncthreads();
    float h = h0[b * H_DIM + lane], c = c0[b * H_DIM + lane];
    const float cwv = cw[lane], cbv = cb[0];

    float dn = done[b];
    const float* xp = g_xg + (size_t)b * 128;
    float pai = xp[lane], paf = xp[32 + lane], pag = xp[64 + lane], pao = xp[96 + lane];

    for (int t = 0; t < T_STEPS; t++) {
        float ai = pai, af = paf, ag = pag, ao = pao, dc = dn;
        if (t < 63) {   // prefetch next step (hides LDG latency behind this step's math)
            int n2 = (t + 1) * B_ENV + b;
            dn = done[n2];
            const float* x2 = g_xg + (size_t)n2 * 128;
            pai = x2[lane]; paf = x2[32 + lane]; pag = x2[64 + lane]; pao = x2[96 + lane];
        }
        float keep = 1.f - dc;
        h *= keep; c *= keep;
        float hv[32];
#pragma unroll
        for (int m = 0; m < 32; m++) hv[m] = __shfl_sync(0xffffffffu, h, m);
#pragma unroll
        for (int m = 0; m < 32; m++) {
            ai += hv[m] * whs[m * 128 + lane];
            af += hv[m] * whs[m * 128 + 32 + lane];
            ag += hv[m] * whs[m * 128 + 64 + lane];
            ao += hv[m] * whs[m * 128 + 96 + lane];
        }
        float gi = sigmoidf_(ai), gf = sigmoidf_(af), gg = tanhf(ag), go = sigmoidf_(ao);
        c = gf * c + gi * gg;
        h = go * tanhf(c);
        float pv = h * cwv;
#pragma unroll
        for (int o = 16; o; o >>= 1) pv += __shfl_xor_sync(0xffffffffu, pv, o);
        if (lane == 0) out[t * B_ENV + b] = pv + cbv;
    }
}

extern "C" void kernel_launch(void* const* d_in, const int* in_sizes, int n_in,
                              void* d_out, int out_size) {
    const float* x    = (const float*)d_in[0];
    const float* done = (const float*)d_in[1];
    const void*  mask = d_in[2];
    const float* h0   = (const float*)d_in[3];
    const float* c0   = (const float*)d_in[4];
    const float* ipw  = (const float*)d_in[5];
    const float* opw  = (const float*)d_in[6];
    const float* wih  = (const float*)d_in[7];
    const float* whh  = (const float*)d_in[8];
    const float* bih  = (const float*)d_in[9];
    const float* bhh  = (const float*)d_in[10];
    const float* cw   = (const float*)d_in[11];
    const float* cb   = (const float*)d_in[12];
    float*       out  = (float*)d_out;
    (void)in_sizes; (void)n_in; (void)out_size;

    cudaFuncSetAttribute(attn_mma, cudaFuncAttributeMaxDynamicSharedMemorySize, SMEM_SZ);
    prep1<<<128, 256>>>(ipw, opw);
    prep2<<<97, 256>>>(wih, bih, bhh);
    attn_mma<<<N_TOT / 2, 256, SMEM_SZ>>>(x, mask);
    lstm_kernel<<<32, 128>>>(done, h0, c0, whh, cw, cb, out);
}

// round 10
// speedup vs baseline: 1.1390x; 1.1390x over previous
#include <cuda_runtime.h>
#include <cuda_bf16.h>
#include <cstdint>

#define T_STEPS 64
#define B_ENV 128
#define L_TOK 64
#define E_DIM 256
#define H_DIM 32
#define N_TOT (T_STEPS * B_ENV)

__device__ float g_M[65536];
__device__ float g_WeffT[65536];
__device__ float g_W2[32768];
__device__ float g_bias[128];
__device__ unsigned short g_MtH[65536]; // bf16 hi of M^T [j][i]
__device__ unsigned short g_MtL[65536]; // bf16 lo
__device__ float g_xg[(size_t)N_TOT * 128];

// ---------------- helpers ----------------
__device__ __forceinline__ uint32_t smem_u32(const void* p) {
    uint32_t a;
    asm("{ .reg .u64 t; cvta.to.shared.u64 t, %1; cvt.u32.u64 %0, t; }" : "=r"(a) : "l"(p));
    return a;
}
__device__ __forceinline__ void ldm4(uint32_t* r, uint32_t a) {
    asm volatile("ldmatrix.sync.aligned.m8n8.x4.shared.b16 {%0,%1,%2,%3}, [%4];"
        : "=r"(r[0]), "=r"(r[1]), "=r"(r[2]), "=r"(r[3]) : "r"(a));
}
__device__ __forceinline__ void mma_bf16(float* d, const uint32_t* a, const uint32_t* b) {
    asm volatile("mma.sync.aligned.m16n8k16.row.col.f32.bf16.bf16.f32 "
        "{%0,%1,%2,%3}, {%4,%5,%6,%7}, {%8,%9}, {%0,%1,%2,%3};"
        : "+f"(d[0]), "+f"(d[1]), "+f"(d[2]), "+f"(d[3])
        : "r"(a[0]), "r"(a[1]), "r"(a[2]), "r"(a[3]), "r"(b[0]), "r"(b[1]));
}
__device__ __forceinline__ uint32_t pack_bf2(__nv_bfloat16 lo, __nv_bfloat16 hi) {
    __nv_bfloat162 p = __halves2bfloat162(lo, hi);
    return *(uint32_t*)&p;
}
__device__ __forceinline__ void cp16(uint32_t dst, const void* src) {
    asm volatile("cp.async.cg.shared.global [%0], [%1], 16;" :: "r"(dst), "l"(src));
}
#define CP_COMMIT() asm volatile("cp.async.commit_group;" ::: "memory")
#define CP_WAIT0()  asm volatile("cp.async.wait_group 0;" ::: "memory")

// ---------------- prep1: M (b<64), WeffT (b>=64) ----------------
__global__ void __launch_bounds__(256) prep1(const float* __restrict__ ipw, const float* __restrict__ opw) {
    __shared__ float As[32][33], Bs[32][33];
    const int b = blockIdx.x, tid = threadIdx.x, tx = tid & 31, ty = tid >> 5;
    float acc[4] = {0.f, 0.f, 0.f, 0.f};
    if (b < 64) {
        int i0 = (b >> 3) * 32, j0 = (b & 7) * 32;
        const float *Wq = ipw, *Wk = ipw + 65536;
        for (int e0 = 0; e0 < 256; e0 += 32) {
#pragma unroll
            for (int r = 0; r < 4; r++) {
                int e = ty + 8 * r;
                As[e][tx] = Wq[(e0 + e) * 256 + i0 + tx];
                Bs[e][tx] = Wk[(e0 + e) * 256 + j0 + tx];
            }
            __syncthreads();
#pragma unroll 8
            for (int e = 0; e < 32; e++) {
                float bv = Bs[e][tx];
#pragma unroll
                for (int r = 0; r < 4; r++) acc[r] += As[e][ty + 8 * r] * bv;
            }
            __syncthreads();
        }
#pragma unroll
        for (int r = 0; r < 4; r++) g_M[(i0 + ty + 8 * r) * 256 + j0 + tx] = acc[r];
    } else {
        int t = b - 64, j0 = (t >> 3) * 32, f0 = (t & 7) * 32;
        const float* Wv = ipw + 131072;
        for (int e0 = 0; e0 < 256; e0 += 32) {
#pragma unroll
            for (int r = 0; r < 4; r++) {
                int e = ty + 8 * r;
                As[e][tx] = Wv[(e0 + e) * 256 + j0 + tx];
                Bs[tx][e] = opw[(f0 + e) * 256 + e0 + tx];
            }
            __syncthreads();
#pragma unroll 8
            for (int e = 0; e < 32; e++) {
                float bv = Bs[e][tx];
#pragma unroll
                for (int r = 0; r < 4; r++) acc[r] += As[e][ty + 8 * r] * bv;
            }
            __syncthreads();
        }
#pragma unroll
        for (int r = 0; r < 4; r++) g_WeffT[(j0 + ty + 8 * r) * 256 + f0 + tx] = acc[r];
    }
}

// ---------------- prep2: Mt split (b<64), W2 (64..95), bias (96) ----------------
__global__ void __launch_bounds__(256) prep2(const float* __restrict__ wih,
                                             const float* __restrict__ bih,
                                             const float* __restrict__ bhh) {
    __shared__ float As[32][33], Bs[32][33];
    const int b = blockIdx.x, tid = threadIdx.x, tx = tid & 31, ty = tid >> 5;
    if (b < 64) {
        int i0 = (b >> 3) * 32, j0 = (b & 7) * 32;
#pragma unroll
        for (int r = 0; r < 4; r++) As[ty + 8 * r][tx] = g_M[(i0 + ty + 8 * r) * 256 + j0 + tx];
        __syncthreads();
#pragma unroll
        for (int r = 0; r < 4; r++) {
            int jj = ty + 8 * r;
            float v = As[tx][jj];
            __nv_bfloat16 h = __float2bfloat16_rn(v);
            __nv_bfloat16 l = __float2bfloat16_rn(v - __bfloat162float(h));
            g_MtH[(j0 + jj) * 256 + i0 + tx] = *(unsigned short*)&h;
            g_MtL[(j0 + jj) * 256 + i0 + tx] = *(unsigned short*)&l;
        }
        return;
    }
    if (b < 96) {
        int t = b - 64, j0 = (t >> 2) * 32, g0 = (t & 3) * 32;
        float acc[4] = {0.f, 0.f, 0.f, 0.f};
        for (int f0 = 0; f0 < 256; f0 += 32) {
#pragma unroll
            for (int r = 0; r < 4; r++) {
                int e = ty + 8 * r;
                As[tx][e] = g_WeffT[(j0 + e) * 256 + f0 + tx];
                Bs[tx][e] = wih[(g0 + e) * 256 + f0 + tx];
            }
            __syncthreads();
#pragma unroll 8
            for (int f = 0; f < 32; f++) {
                float bv = Bs[f][tx];
#pragma unroll
                for (int r = 0; r < 4; r++) acc[r] += As[f][ty + 8 * r] * bv;
            }
            __syncthreads();
        }
#pragma unroll
        for (int r = 0; r < 4; r++) g_W2[(j0 + ty + 8 * r) * 128 + g0 + tx] = acc[r];
        return;
    }
    if (tid < 128) g_bias[tid] = bih[tid] + bhh[tid];
}

// ---------------- attention (R8 config: 512 thr, 16 warps, m16n32) ----------
#define XH_OFF   0        /* 2 x 64 x 512 */
#define XL_OFF   65536
#define STGH_OFF 131072   /* 64 x 512 */
#define STGL_OFF 163840
#define TSH_OFF  196608   /* 2 x 64 x 128 */
#define TSL_OFF  212992
#define SMEM_SZ  229376
#define SC_OFF   STGH_OFF          /* f32 [2][64][68] after GEMMs */
#define DF_OFF   TSH_OFF           /* overlays ts after GEMMs */
#define WGT_OFF  (TSH_OFF + 512)
#define XW_OFF   (TSH_OFF + 1024)
#define MODE_OFF (TSH_OFF + 3072)

__global__ void __launch_bounds__(512, 1) attn_mma(const float* __restrict__ x,
                                                   const void* __restrict__ mask) {
    extern __shared__ char smem[];
    const uint32_t sb = smem_u32(smem);
    const int tid = threadIdx.x, lane = tid & 31, w = tid >> 5;
    const int n0 = blockIdx.x * 2;

    // stage chunk 0 of Mt (hi+lo) via cp.async
    for (int u = tid; u < 4096; u += 512) {
        int buf = u >> 11, v = u & 2047;
        int row = v >> 5, c16 = (v & 31) << 4;
        uint32_t d = (buf ? STGL_OFF : STGH_OFF) + row * 512 + (c16 ^ ((row & 7) << 4));
        cp16(sb + d, (const uint4*)(buf ? g_MtL : g_MtH) + v);
    }
    CP_COMMIT();

    // load x (2 samples) f32 -> bf16 hi/lo smem (swizzled)
    const float2* xb = (const float2*)(x + (size_t)n0 * (L_TOK * E_DIM));
    for (int idx = tid; idx < 16384; idx += 512) {
        int s = idx >> 13, r = (idx >> 7) & 63, cp = idx & 127;
        float2 v = xb[idx];
        __nv_bfloat16 h0 = __float2bfloat16_rn(v.x), h1 = __float2bfloat16_rn(v.y);
        __nv_bfloat16 l0 = __float2bfloat16_rn(v.x - __bfloat162float(h0));
        __nv_bfloat16 l1 = __float2bfloat16_rn(v.y - __bfloat162float(h1));
        uint32_t boff = (uint32_t)(s * 32768 + r * 512 + ((cp * 4) ^ ((r & 7) << 4)));
        *(uint32_t*)(smem + XH_OFF + boff) = pack_bf2(h0, h1);
        *(uint32_t*)(smem + XL_OFF + boff) = pack_bf2(l0, l1);
    }
    CP_WAIT0();
    __syncthreads();

    // warp layout: s = w>>3 (sample), tile m16 x n32
    const int s = w >> 3, w8 = w & 7, mg = w8 >> 1, ng = w8 & 1;
    const int arow = mg * 16 + (lane & 15);
    const uint32_t a_rot = (arow & 7) << 4, a_klo = (lane >> 4) << 4;
    const uint32_t axh = sb + XH_OFF + s * 32768 + arow * 512;
    const uint32_t axl = sb + XL_OFF + s * 32768 + arow * 512;
    const uint32_t ath = sb + TSH_OFF + s * 8192 + arow * 128;
    const uint32_t atl = sb + TSL_OFF + s * 8192 + arow * 128;
    const int br0 = ng * 32 + (lane & 7) + ((lane & 16) >> 1), br1 = br0 + 16;
    const uint32_t b_rot0 = (br0 & 7) << 4, b_rot1 = (br1 & 7) << 4;
    const uint32_t bklo = ((lane >> 3) & 1) << 4;

    float acc2[4][4];
#pragma unroll
    for (int nt = 0; nt < 4; nt++)
#pragma unroll
        for (int q = 0; q < 4; q++) acc2[nt][q] = 0.f;

    for (int ch = 0; ch < 4; ch++) {
        // GEMM1 chunk: ts_ch[64][64] = x_s @ Mt_ch^T (3 terms, K=256)
        float acc1[4][4];
#pragma unroll
        for (int nt = 0; nt < 4; nt++)
#pragma unroll
            for (int q = 0; q < 4; q++) acc1[nt][q] = 0.f;
        const uint32_t sgh0 = sb + STGH_OFF + br0 * 512, sgh1 = sb + STGH_OFF + br1 * 512;
        const uint32_t sgl0 = sb + STGL_OFF + br0 * 512, sgl1 = sb + STGL_OFF + br1 * 512;
#pragma unroll 4
        for (int ks = 0; ks < 16; ks++) {
            uint32_t kb = ks * 32;
            uint32_t Ah[4], Al[4], Bh0[4], Bh1[4], Bl0[4], Bl1[4];
            ldm4(Ah, axh + ((kb + a_klo) ^ a_rot));
            ldm4(Al, axl + ((kb + a_klo) ^ a_rot));
            ldm4(Bh0, sgh0 + ((kb + bklo) ^ b_rot0));
            ldm4(Bh1, sgh1 + ((kb + bklo) ^ b_rot1));
            ldm4(Bl0, sgl0 + ((kb + bklo) ^ b_rot0));
            ldm4(Bl1, sgl1 + ((kb + bklo) ^ b_rot1));
            mma_bf16(acc1[0], Ah, Bh0); mma_bf16(acc1[1], Ah, Bh0 + 2);
            mma_bf16(acc1[2], Ah, Bh1); mma_bf16(acc1[3], Ah, Bh1 + 2);
            mma_bf16(acc1[0], Al, Bh0); mma_bf16(acc1[1], Al, Bh0 + 2);
            mma_bf16(acc1[2], Al, Bh1); mma_bf16(acc1[3], Al, Bh1 + 2);
            mma_bf16(acc1[0], Ah, Bl0); mma_bf16(acc1[1], Ah, Bl0 + 2);
            mma_bf16(acc1[2], Ah, Bl1); mma_bf16(acc1[3], Ah, Bl1 + 2);
        }
        // write ts chunk (bf16 hi/lo, swizzled 128B rows)
#pragma unroll
        for (int nt = 0; nt < 4; nt++) {
            int col = ng * 32 + nt * 8 + 2 * (lane & 3);
            int r0 = mg * 16 + (lane >> 2);
#pragma unroll
            for (int hh = 0; hh < 2; hh++) {
                int rr = r0 + 8 * hh;
                float v0 = acc1[nt][2 * hh], v1 = acc1[nt][2 * hh + 1];
                __nv_bfloat16 h0 = __float2bfloat16_rn(v0), h1 = __float2bfloat16_rn(v1);
                __nv_bfloat16 l0 = __float2bfloat16_rn(v0 - __bfloat162float(h0));
                __nv_bfloat16 l1 = __float2bfloat16_rn(v1 - __bfloat162float(h1));
                uint32_t boff = (uint32_t)(s * 8192 + rr * 128 + ((col * 2) ^ ((rr & 7) << 4)));
                *(uint32_t*)(smem + TSH_OFF + boff) = pack_bf2(h0, h1);
                *(uint32_t*)(smem + TSL_OFF + boff) = pack_bf2(l0, l1);
            }
        }
        __syncthreads();   // ts visible; GEMM1 done reading STG

        // prefetch next Mt chunk (overlaps GEMM2)
        if (ch < 3) {
            for (int u = tid; u < 4096; u += 512) {
                int buf = u >> 11, v = u & 2047;
                int row = v >> 5, c16 = (v & 31) << 4;
                uint32_t d = (buf ? STGL_OFF : STGH_OFF) + row * 512 + (c16 ^ ((row & 7) << 4));
                cp16(sb + d, (const uint4*)((buf ? g_MtL : g_MtH) + (ch + 1) * 16384) + v);
            }
            CP_COMMIT();
        }

        // GEMM2 partial: sc_s += ts_ch @ x_ch^T (3 terms, K=64)
        const uint32_t bxh0 = sb + XH_OFF + s * 32768 + br0 * 512;
        const uint32_t bxh1 = sb + XH_OFF + s * 32768 + br1 * 512;
        const uint32_t bxl0 = sb + XL_OFF + s * 32768 + br0 * 512;
        const uint32_t bxl1 = sb + XL_OFF + s * 32768 + br1 * 512;
#pragma unroll
        for (int ks = 0; ks < 4; ks++) {
            uint32_t kb = ks * 32, xc = ch * 128 + kb + bklo;
            uint32_t Ah[4], Al[4], Bh0[4], Bh1[4], Bl0[4], Bl1[4];
            ldm4(Ah, ath + ((kb + a_klo) ^ a_rot));
            ldm4(Al, atl + ((kb + a_klo) ^ a_rot));
            ldm4(Bh0, bxh0 + (xc ^ b_rot0));
            ldm4(Bh1, bxh1 + (xc ^ b_rot1));
            ldm4(Bl0, bxl0 + (xc ^ b_rot0));
            ldm4(Bl1, bxl1 + (xc ^ b_rot1));
            mma_bf16(acc2[0], Ah, Bh0); mma_bf16(acc2[1], Ah, Bh0 + 2);
            mma_bf16(acc2[2], Ah, Bh1); mma_bf16(acc2[3], Ah, Bh1 + 2);
            mma_bf16(acc2[0], Al, Bh0); mma_bf16(acc2[1], Al, Bh0 + 2);
            mma_bf16(acc2[2], Al, Bh1); mma_bf16(acc2[3], Al, Bh1 + 2);
            mma_bf16(acc2[0], Ah, Bl0); mma_bf16(acc2[1], Ah, Bl0 + 2);
            mma_bf16(acc2[2], Ah, Bl1); mma_bf16(acc2[3], Ah, Bl1 + 2);
        }
        if (ch < 3) { CP_WAIT0(); }
        __syncthreads();   // next GEMM1 may read STG; ts rewrite safe
    }

    // ---- write sc (overlay STG), scaled; warp 0 detects mask dtype ----
    float* scp = (float*)(smem + SC_OFF) + s * 4352;
#pragma unroll
    for (int nt = 0; nt < 4; nt++) {
        int col = ng * 32 + nt * 8 + 2 * (lane & 3);
        int r0 = mg * 16 + (lane >> 2);
        scp[r0 * 68 + col]           = acc2[nt][0] * 0.0625f;
        scp[r0 * 68 + col + 1]       = acc2[nt][1] * 0.0625f;
        scp[(r0 + 8) * 68 + col]     = acc2[nt][2] * 0.0625f;
        scp[(r0 + 8) * 68 + col + 1] = acc2[nt][3] * 0.0625f;
    }
    if (w == 0) {
        const unsigned* mw = (const unsigned*)mask;
        int f = 0, g = 0;
        for (int i = lane; i < 2048; i += 32) {
            unsigned v = mw[i];
            f |= (v == 0x3F800000u);
            g |= (v > 1u);
        }
        f = __any_sync(0xffffffffu, f);
        g = __any_sync(0xffffffffu, g);
        if (!lane) *(int*)(smem + MODE_OFF) = f ? 2 : (g ? 1 : 0);
    }
    __syncthreads();

    // ---- dropped flags + wgt init ----
    float* dfp = (float*)(smem + DF_OFF);
    float* wgt = (float*)(smem + WGT_OFF);
    float* xw  = (float*)(smem + XW_OFF);
    if (tid < 128) {
        int mode = *(int*)(smem + MODE_OFF);
        size_t mi = (size_t)n0 * 64 + tid;
        bool at;
        if (mode == 0)      at = ((const int*)mask)[mi] != 0;
        else if (mode == 1) at = ((const uint8_t*)mask)[mi] != 0;
        else                at = ((const float*)mask)[mi] != 0.f;
        dfp[tid] = at ? 0.f : 1.f;
        wgt[tid] = 0.f;
    }
    __syncthreads();

    // ---- softmax: 8 rows/warp ----
    {
        const int w8s = w & 7;
        const float* scs = (const float*)(smem + SC_OFF) + s * 4352;
        const float* dfs = dfp + s * 64;
        const bool dk0 = dfs[lane] > 0.5f, dk1 = dfs[lane + 32] > 0.5f;
        float wa0 = 0.f, wa1 = 0.f;
#pragma unroll
        for (int r = 0; r < 8; r++) {
            int lq = w8s * 8 + r;
            bool dq = dfs[lq] > 0.5f;
            float s0 = scs[lq * 68 + lane], s1 = scs[lq * 68 + lane + 32];
            if (dq && dk0) s0 = -1e30f;
            if (dq && dk1) s1 = -1e30f;
            float m = fmaxf(s0, s1);
#pragma unroll
            for (int o = 16; o; o >>= 1) m = fmaxf(m, __shfl_xor_sync(0xffffffffu, m, o));
            float e0 = __expf(s0 - m), e1 = __expf(s1 - m);
            float ss = e0 + e1;
#pragma unroll
            for (int o = 16; o; o >>= 1) ss += __shfl_xor_sync(0xffffffffu, ss, o);
            float inv = 1.f / ss;
            wa0 += e0 * inv;
            wa1 += e1 * inv;
        }
        atomicAdd(&wgt[s * 64 + lane], wa0);
        atomicAdd(&wgt[s * 64 + lane + 32], wa1);
    }
    __syncthreads();

    // ---- xw[s][j] = sum_k wgt[s][k] * x[s][k][j] (hi+lo, swizzled) ----
    {
        const int ss = tid >> 8, j = tid & 255;
        float a = 0.f;
#pragma unroll 8
        for (int k = 0; k < 64; k++) {
            uint32_t boff = (uint32_t)(ss * 32768 + k * 512 + ((2 * j) ^ ((k & 7) << 4)));
            a += wgt[ss * 64 + k] *
                 (__bfloat162float(*(__nv_bfloat16*)(smem + XH_OFF + boff)) +
                  __bfloat162float(*(__nv_bfloat16*)(smem + XL_OFF + boff)));
        }
        xw[tid] = a;
    }
    __syncthreads();

    // ---- xg[s][g] = bias[g] + sum_j xw[s][j] * W2[j][g] ----
    if (tid < 256) {
        const int ss = tid >> 7, g = tid & 127;
        float a = g_bias[g];
        const float* xwp = xw + ss * 256;
        const float* Wp = g_W2 + g;
#pragma unroll 4
        for (int j = 0; j < 256; j++) a += xwp[j] * __ldg(Wp + (size_t)j * 128);
        g_xg[(size_t)(n0 + ss) * 128 + g] = a;
    }
}

// ---------------- LSTM scan + critic (R9 version: pipelined, 32x4) ----------
__device__ __forceinline__ float sigmoidf_(float v) { return 1.f / (1.f + __expf(-v)); }

__global__ void __launch_bounds__(128) lstm_kernel(const float* __restrict__ done,
                                                   const float* __restrict__ h0,
                                                   const float* __restrict__ c0,
                                                   const float* __restrict__ whh,
                                                   const float* __restrict__ cw,
                                                   const float* __restrict__ cb,
                                                   float* __restrict__ out) {
    __shared__ float whs[32 * 128];
    const int tid = threadIdx.x, lane = tid & 31, w = tid >> 5;
    const int b = blockIdx.x * 4 + w;
    for (int idx = tid; idx < 4096; idx += 128) {
        int g = idx >> 5, m = idx & 31;
        whs[m * 128 + g] = whh[idx];
    }
    __syncthreads();
    float h = h0[b * H_DIM + lane], c = c0[b * H_DIM + lane];
    const float cwv = cw[lane], cbv = cb[0];

    float dn = done[b];
    const float* xp = g_xg + (size_t)b * 128;
    float pai = xp[lane], paf = xp[32 + lane], pag = xp[64 + lane], pao = xp[96 + lane];

    for (int t = 0; t < T_STEPS; t++) {
        float ai = pai, af = paf, ag = pag, ao = pao, dc = dn;
        if (t < 63) {
            int n2 = (t + 1) * B_ENV + b;
            dn = done[n2];
            const float* x2 = g_xg + (size_t)n2 * 128;
            pai = x2[lane]; paf = x2[32 + lane]; pag = x2[64 + lane]; pao = x2[96 + lane];
        }
        float keep = 1.f - dc;
        h *= keep; c *= keep;
        float hv[32];
#pragma unroll
        for (int m = 0; m < 32; m++) hv[m] = __shfl_sync(0xffffffffu, h, m);
#pragma unroll
        for (int m = 0; m < 32; m++) {
            ai += hv[m] * whs[m * 128 + lane];
            af += hv[m] * whs[m * 128 + 32 + lane];
            ag += hv[m] * whs[m * 128 + 64 + lane];
            ao += hv[m] * whs[m * 128 + 96 + lane];
        }
        float gi = sigmoidf_(ai), gf = sigmoidf_(af), gg = tanhf(ag), go = sigmoidf_(ao);
        c = gf * c + gi * gg;
        h = go * tanhf(c);
        float pv = h * cwv;
#pragma unroll
        for (int o = 16; o; o >>= 1) pv += __shfl_xor_sync(0xffffffffu, pv, o);
        if (lane == 0) out[t * B_ENV + b] = pv + cbv;
    }
}

extern "C" void kernel_launch(void* const* d_in, const int* in_sizes, int n_in,
                              void* d_out, int out_size) {
    const float* x    = (const float*)d_in[0];
    const float* done = (const float*)d_in[1];
    const void*  mask = d_in[2];
    const float* h0   = (const float*)d_in[3];
    const float* c0   = (const float*)d_in[4];
    const float* ipw  = (const float*)d_in[5];
    const float* opw  = (const float*)d_in[6];
    const float* wih  = (const float*)d_in[7];
    const float* whh  = (const float*)d_in[8];
    const float* bih  = (const float*)d_in[9];
    const float* bhh  = (const float*)d_in[10];
    const float* cw   = (const float*)d_in[11];
    const float* cb   = (const float*)d_in[12];
    float*       out  = (float*)d_out;
    (void)in_sizes; (void)n_in; (void)out_size;

    cudaFuncSetAttribute(attn_mma, cudaFuncAttributeMaxDynamicSharedMemorySize, SMEM_SZ);
    prep1<<<128, 256>>>(ipw, opw);
    prep2<<<97, 256>>>(wih, bih, bhh);
    attn_mma<<<N_TOT / 2, 512, SMEM_SZ>>>(x, mask);
    lstm_kernel<<<32, 128>>>(done, h0, c0, whh, cw, cb, out);
}

// round 11
// speedup vs baseline: 1.1783x; 1.0345x over previous
#include <cuda_runtime.h>
#include <cuda_bf16.h>
#include <cstdint>

#define T_STEPS 64
#define B_ENV 128
#define L_TOK 64
#define E_DIM 256
#define H_DIM 32
#define N_TOT (T_STEPS * B_ENV)

__device__ float g_M[65536];
__device__ float g_WeffT[65536];
__device__ float g_W2[32768];
__device__ float g_bias[128];
__device__ unsigned short g_MtH[65536]; // bf16 hi of M^T [j][i]
__device__ unsigned short g_MtL[65536]; // bf16 lo
__device__ float g_xg[(size_t)N_TOT * 128];

// ---------------- helpers ----------------
__device__ __forceinline__ uint32_t smem_u32(const void* p) {
    uint32_t a;
    asm("{ .reg .u64 t; cvta.to.shared.u64 t, %1; cvt.u32.u64 %0, t; }" : "=r"(a) : "l"(p));
    return a;
}
__device__ __forceinline__ void ldm4(uint32_t* r, uint32_t a) {
    asm volatile("ldmatrix.sync.aligned.m8n8.x4.shared.b16 {%0,%1,%2,%3}, [%4];"
        : "=r"(r[0]), "=r"(r[1]), "=r"(r[2]), "=r"(r[3]) : "r"(a));
}
__device__ __forceinline__ void mma_bf16(float* d, const uint32_t* a, const uint32_t* b) {
    asm volatile("mma.sync.aligned.m16n8k16.row.col.f32.bf16.bf16.f32 "
        "{%0,%1,%2,%3}, {%4,%5,%6,%7}, {%8,%9}, {%0,%1,%2,%3};"
        : "+f"(d[0]), "+f"(d[1]), "+f"(d[2]), "+f"(d[3])
        : "r"(a[0]), "r"(a[1]), "r"(a[2]), "r"(a[3]), "r"(b[0]), "r"(b[1]));
}
__device__ __forceinline__ uint32_t pack_bf2(__nv_bfloat16 lo, __nv_bfloat16 hi) {
    __nv_bfloat162 p = __halves2bfloat162(lo, hi);
    return *(uint32_t*)&p;
}
__device__ __forceinline__ void cp16(uint32_t dst, const void* src) {
    asm volatile("cp.async.cg.shared.global [%0], [%1], 16;" :: "r"(dst), "l"(src));
}
#define CP_COMMIT() asm volatile("cp.async.commit_group;" ::: "memory")
#define CP_WAIT0()  asm volatile("cp.async.wait_group 0;" ::: "memory")

// ---------------- prep1: M (b<64), WeffT (b>=64) ----------------
__global__ void __launch_bounds__(256) prep1(const float* __restrict__ ipw, const float* __restrict__ opw) {
    __shared__ float As[32][33], Bs[32][33];
    const int b = blockIdx.x, tid = threadIdx.x, tx = tid & 31, ty = tid >> 5;
    float acc[4] = {0.f, 0.f, 0.f, 0.f};
    if (b < 64) {
        int i0 = (b >> 3) * 32, j0 = (b & 7) * 32;
        const float *Wq = ipw, *Wk = ipw + 65536;
        for (int e0 = 0; e0 < 256; e0 += 32) {
#pragma unroll
            for (int r = 0; r < 4; r++) {
                int e = ty + 8 * r;
                As[e][tx] = Wq[(e0 + e) * 256 + i0 + tx];
                Bs[e][tx] = Wk[(e0 + e) * 256 + j0 + tx];
            }
            __syncthreads();
#pragma unroll 8
            for (int e = 0; e < 32; e++) {
                float bv = Bs[e][tx];
#pragma unroll
                for (int r = 0; r < 4; r++) acc[r] += As[e][ty + 8 * r] * bv;
            }
            __syncthreads();
        }
#pragma unroll
        for (int r = 0; r < 4; r++) g_M[(i0 + ty + 8 * r) * 256 + j0 + tx] = acc[r];
    } else {
        int t = b - 64, j0 = (t >> 3) * 32, f0 = (t & 7) * 32;
        const float* Wv = ipw + 131072;
        for (int e0 = 0; e0 < 256; e0 += 32) {
#pragma unroll
            for (int r = 0; r < 4; r++) {
                int e = ty + 8 * r;
                As[e][tx] = Wv[(e0 + e) * 256 + j0 + tx];
                Bs[tx][e] = opw[(f0 + e) * 256 + e0 + tx];
            }
            __syncthreads();
#pragma unroll 8
            for (int e = 0; e < 32; e++) {
                float bv = Bs[e][tx];
#pragma unroll
                for (int r = 0; r < 4; r++) acc[r] += As[e][ty + 8 * r] * bv;
            }
            __syncthreads();
        }
#pragma unroll
        for (int r = 0; r < 4; r++) g_WeffT[(j0 + ty + 8 * r) * 256 + f0 + tx] = acc[r];
    }
}

// ---------------- prep2: Mt split (b<64), W2 (64..95), bias (96) ----------------
__global__ void __launch_bounds__(256) prep2(const float* __restrict__ wih,
                                             const float* __restrict__ bih,
                                             const float* __restrict__ bhh) {
    __shared__ float As[32][33], Bs[32][33];
    const int b = blockIdx.x, tid = threadIdx.x, tx = tid & 31, ty = tid >> 5;
    if (b < 64) {
        int i0 = (b >> 3) * 32, j0 = (b & 7) * 32;
#pragma unroll
        for (int r = 0; r < 4; r++) As[ty + 8 * r][tx] = g_M[(i0 + ty + 8 * r) * 256 + j0 + tx];
        __syncthreads();
#pragma unroll
        for (int r = 0; r < 4; r++) {
            int jj = ty + 8 * r;
            float v = As[tx][jj];
            __nv_bfloat16 h = __float2bfloat16_rn(v);
            __nv_bfloat16 l = __float2bfloat16_rn(v - __bfloat162float(h));
            g_MtH[(j0 + jj) * 256 + i0 + tx] = *(unsigned short*)&h;
            g_MtL[(j0 + jj) * 256 + i0 + tx] = *(unsigned short*)&l;
        }
        return;
    }
    if (b < 96) {
        int t = b - 64, j0 = (t >> 2) * 32, g0 = (t & 3) * 32;
        float acc[4] = {0.f, 0.f, 0.f, 0.f};
        for (int f0 = 0; f0 < 256; f0 += 32) {
#pragma unroll
            for (int r = 0; r < 4; r++) {
                int e = ty + 8 * r;
                As[tx][e] = g_WeffT[(j0 + e) * 256 + f0 + tx];
                Bs[tx][e] = wih[(g0 + e) * 256 + f0 + tx];
            }
            __syncthreads();
#pragma unroll 8
            for (int f = 0; f < 32; f++) {
                float bv = Bs[f][tx];
#pragma unroll
                for (int r = 0; r < 4; r++) acc[r] += As[f][ty + 8 * r] * bv;
            }
            __syncthreads();
        }
#pragma unroll
        for (int r = 0; r < 4; r++) g_W2[(j0 + ty + 8 * r) * 128 + g0 + tx] = acc[r];
        return;
    }
    if (tid < 128) g_bias[tid] = bih[tid] + bhh[tid];
}

// ---------------- attention: 1 sample/CTA, 8 warps, 2 CTAs/SM ----------------
// x rows 512 B swizzled; single 32KB M stage (two-pass terms); ts rows 128 B.
#define XH_OFF   0        /* 64 x 512 */
#define XL_OFF   32768
#define STG_OFF  65536    /* 64 x 512: holds Mt hi OR lo of current chunk */
#define TSH_OFF  98304    /* 64 x 128 */
#define TSL_OFF  106496
#define SMEM_SZ  114688
#define SC_OFF   STG_OFF           /* f32 [64][68] = 17408, after GEMMs */
#define DF_OFF   TSH_OFF           /* 64 f32, overlays ts after GEMMs */
#define WGT_OFF  (TSH_OFF + 256)
#define XW_OFF   (TSH_OFF + 512)   /* 256 f32 */
#define MODE_OFF (TSH_OFF + 2048)

__global__ void __launch_bounds__(256, 2) attn_mma(const float* __restrict__ x,
                                                   const void* __restrict__ mask) {
    extern __shared__ char smem[];
    const uint32_t sb = smem_u32(smem);
    const int tid = threadIdx.x, lane = tid & 31, w = tid >> 5;
    const int n = blockIdx.x;

    // stage chunk 0 of MtH via cp.async (2048 x 16B)
    for (int u = tid; u < 2048; u += 256) {
        int row = u >> 5, c16 = (u & 31) << 4;
        uint32_t d = STG_OFF + row * 512 + (c16 ^ ((row & 7) << 4));
        cp16(sb + d, (const uint4*)g_MtH + u);
    }
    CP_COMMIT();

    // load x (1 sample) f32 -> bf16 hi/lo smem (swizzled)
    const float2* xb = (const float2*)(x + (size_t)n * (L_TOK * E_DIM));
    for (int idx = tid; idx < 8192; idx += 256) {
        int r = idx >> 7, cp = idx & 127;
        float2 v = xb[idx];
        __nv_bfloat16 h0 = __float2bfloat16_rn(v.x), h1 = __float2bfloat16_rn(v.y);
        __nv_bfloat16 l0 = __float2bfloat16_rn(v.x - __bfloat162float(h0));
        __nv_bfloat16 l1 = __float2bfloat16_rn(v.y - __bfloat162float(h1));
        uint32_t boff = (uint32_t)(r * 512 + ((cp * 4) ^ ((r & 7) << 4)));
        *(uint32_t*)(smem + XH_OFF + boff) = pack_bf2(h0, h1);
        *(uint32_t*)(smem + XL_OFF + boff) = pack_bf2(l0, l1);
    }
    CP_WAIT0();
    __syncthreads();

    // warp layout: 4x2 grid of m16n32 tiles over 64x64 outputs
    const int mg = w >> 1, ng = w & 1;
    const int arow = mg * 16 + (lane & 15);
    const uint32_t a_rot = (arow & 7) << 4, a_klo = (lane >> 4) << 4;
    const uint32_t axh = sb + XH_OFF + arow * 512;
    const uint32_t axl = sb + XL_OFF + arow * 512;
    const uint32_t ath = sb + TSH_OFF + arow * 128;
    const uint32_t atl = sb + TSL_OFF + arow * 128;
    const int br0 = ng * 32 + (lane & 7) + ((lane & 16) >> 1), br1 = br0 + 16;
    const uint32_t b_rot0 = (br0 & 7) << 4, b_rot1 = (br1 & 7) << 4;
    const uint32_t bklo = ((lane >> 3) & 1) << 4;

    float acc2[4][4];
#pragma unroll
    for (int nt = 0; nt < 4; nt++)
#pragma unroll
        for (int q = 0; q < 4; q++) acc2[nt][q] = 0.f;

    for (int ch = 0; ch < 4; ch++) {
        float acc1[4][4];
#pragma unroll
        for (int nt = 0; nt < 4; nt++)
#pragma unroll
            for (int q = 0; q < 4; q++) acc1[nt][q] = 0.f;
        const uint32_t sg0 = sb + STG_OFF + br0 * 512, sg1 = sb + STG_OFF + br1 * 512;

        // pass1: (x_hi + x_lo) @ Mt_hi  (STG holds hi)
#pragma unroll 4
        for (int ks = 0; ks < 16; ks++) {
            uint32_t kb = ks * 32;
            uint32_t Ah[4], Al[4], B0[4], B1[4];
            ldm4(Ah, axh + ((kb + a_klo) ^ a_rot));
            ldm4(Al, axl + ((kb + a_klo) ^ a_rot));
            ldm4(B0, sg0 + ((kb + bklo) ^ b_rot0));
            ldm4(B1, sg1 + ((kb + bklo) ^ b_rot1));
            mma_bf16(acc1[0], Ah, B0); mma_bf16(acc1[1], Ah, B0 + 2);
            mma_bf16(acc1[2], Ah, B1); mma_bf16(acc1[3], Ah, B1 + 2);
            mma_bf16(acc1[0], Al, B0); mma_bf16(acc1[1], Al, B0 + 2);
            mma_bf16(acc1[2], Al, B1); mma_bf16(acc1[3], Al, B1 + 2);
        }
        __syncthreads();   // done reading STG(hi)

        // swap in Mt_lo for this chunk
        for (int u = tid; u < 2048; u += 256) {
            int row = u >> 5, c16 = (u & 31) << 4;
            uint32_t d = STG_OFF + row * 512 + (c16 ^ ((row & 7) << 4));
            cp16(sb + d, (const uint4*)(g_MtL + ch * 16384) + u);
        }
        CP_COMMIT(); CP_WAIT0();
        __syncthreads();

        // pass2: x_hi @ Mt_lo
#pragma unroll 4
        for (int ks = 0; ks < 16; ks++) {
            uint32_t kb = ks * 32;
            uint32_t Ah[4], B0[4], B1[4];
            ldm4(Ah, axh + ((kb + a_klo) ^ a_rot));
            ldm4(B0, sg0 + ((kb + bklo) ^ b_rot0));
            ldm4(B1, sg1 + ((kb + bklo) ^ b_rot1));
            mma_bf16(acc1[0], Ah, B0); mma_bf16(acc1[1], Ah, B0 + 2);
            mma_bf16(acc1[2], Ah, B1); mma_bf16(acc1[3], Ah, B1 + 2);
        }

        // write ts chunk (bf16 hi/lo, swizzled 128B rows)
#pragma unroll
        for (int nt = 0; nt < 4; nt++) {
            int col = ng * 32 + nt * 8 + 2 * (lane & 3);
            int r0 = mg * 16 + (lane >> 2);
#pragma unroll
            for (int hh = 0; hh < 2; hh++) {
                int rr = r0 + 8 * hh;
                float v0 = acc1[nt][2 * hh], v1 = acc1[nt][2 * hh + 1];
                __nv_bfloat16 h0 = __float2bfloat16_rn(v0), h1 = __float2bfloat16_rn(v1);
                __nv_bfloat16 l0 = __float2bfloat16_rn(v0 - __bfloat162float(h0));
                __nv_bfloat16 l1 = __float2bfloat16_rn(v1 - __bfloat162float(h1));
                uint32_t boff = (uint32_t)(rr * 128 + ((col * 2) ^ ((rr & 7) << 4)));
                *(uint32_t*)(smem + TSH_OFF + boff) = pack_bf2(h0, h1);
                *(uint32_t*)(smem + TSL_OFF + boff) = pack_bf2(l0, l1);
            }
        }
        __syncthreads();   // ts visible; done reading STG(lo)

        // prefetch next chunk's Mt_hi (overlaps GEMM2)
        if (ch < 3) {
            for (int u = tid; u < 2048; u += 256) {
                int row = u >> 5, c16 = (u & 31) << 4;
                uint32_t d = STG_OFF + row * 512 + (c16 ^ ((row & 7) << 4));
                cp16(sb + d, (const uint4*)(g_MtH + (ch + 1) * 16384) + u);
            }
            CP_COMMIT();
        }

        // GEMM2 partial: sc += ts_ch @ x_ch^T (3 terms, K=64)
        const uint32_t bxh0 = sb + XH_OFF + br0 * 512, bxh1 = sb + XH_OFF + br1 * 512;
        const uint32_t bxl0 = sb + XL_OFF + br0 * 512, bxl1 = sb + XL_OFF + br1 * 512;
#pragma unroll
        for (int ks = 0; ks < 4; ks++) {
            uint32_t kb = ks * 32, xc = ch * 128 + kb + bklo;
            uint32_t Ah[4], Al[4], Bh0[4], Bh1[4], Bl0[4], Bl1[4];
            ldm4(Ah, ath + ((kb + a_klo) ^ a_rot));
            ldm4(Al, atl + ((kb + a_klo) ^ a_rot));
            ldm4(Bh0, bxh0 + (xc ^ b_rot0));
            ldm4(Bh1, bxh1 + (xc ^ b_rot1));
            ldm4(Bl0, bxl0 + (xc ^ b_rot0));
            ldm4(Bl1, bxl1 + (xc ^ b_rot1));
            mma_bf16(acc2[0], Ah, Bh0); mma_bf16(acc2[1], Ah, Bh0 + 2);
            mma_bf16(acc2[2], Ah, Bh1); mma_bf16(acc2[3], Ah, Bh1 + 2);
            mma_bf16(acc2[0], Al, Bh0); mma_bf16(acc2[1], Al, Bh0 + 2);
            mma_bf16(acc2[2], Al, Bh1); mma_bf16(acc2[3], Al, Bh1 + 2);
            mma_bf16(acc2[0], Ah, Bl0); mma_bf16(acc2[1], Ah, Bl0 + 2);
            mma_bf16(acc2[2], Ah, Bl1); mma_bf16(acc2[3], Ah, Bl1 + 2);
        }
        if (ch < 3) { CP_WAIT0(); }
        __syncthreads();
    }

    // ---- write sc (overlay STG), scaled; warp 0 detects mask dtype ----
    float* scp = (float*)(smem + SC_OFF);
#pragma unroll
    for (int nt = 0; nt < 4; nt++) {
        int col = ng * 32 + nt * 8 + 2 * (lane & 3);
        int r0 = mg * 16 + (lane >> 2);
        scp[r0 * 68 + col]           = acc2[nt][0] * 0.0625f;
        scp[r0 * 68 + col + 1]       = acc2[nt][1] * 0.0625f;
        scp[(r0 + 8) * 68 + col]     = acc2[nt][2] * 0.0625f;
        scp[(r0 + 8) * 68 + col + 1] = acc2[nt][3] * 0.0625f;
    }
    if (w == 0) {
        const unsigned* mw = (const unsigned*)mask;
        int f = 0, g = 0;
        for (int i = lane; i < 2048; i += 32) {
            unsigned v = mw[i];
            f |= (v == 0x3F800000u);
            g |= (v > 1u);
        }
        f = __any_sync(0xffffffffu, f);
        g = __any_sync(0xffffffffu, g);
        if (!lane) *(int*)(smem + MODE_OFF) = f ? 2 : (g ? 1 : 0);
    }
    __syncthreads();

    // ---- dropped flags + wgt init ----
    float* dfp = (float*)(smem + DF_OFF);
    float* wgt = (float*)(smem + WGT_OFF);
    float* xw  = (float*)(smem + XW_OFF);
    if (tid < 64) {
        int mode = *(int*)(smem + MODE_OFF);
        size_t mi = (size_t)n * 64 + tid;
        bool at;
        if (mode == 0)      at = ((const int*)mask)[mi] != 0;
        else if (mode == 1) at = ((const uint8_t*)mask)[mi] != 0;
        else                at = ((const float*)mask)[mi] != 0.f;
        dfp[tid] = at ? 0.f : 1.f;
        wgt[tid] = 0.f;
    }
    __syncthreads();

    // ---- softmax: 8 rows/warp ----
    {
        const bool dk0 = dfp[lane] > 0.5f, dk1 = dfp[lane + 32] > 0.5f;
        float wa0 = 0.f, wa1 = 0.f;
#pragma unroll
        for (int r = 0; r < 8; r++) {
            int lq = w * 8 + r;
            bool dq = dfp[lq] > 0.5f;
            float s0 = scp[lq * 68 + lane], s1 = scp[lq * 68 + lane + 32];
            if (dq && dk0) s0 = -1e30f;
            if (dq && dk1) s1 = -1e30f;
            float m = fmaxf(s0, s1);
#pragma unroll
            for (int o = 16; o; o >>= 1) m = fmaxf(m, __shfl_xor_sync(0xffffffffu, m, o));
            float e0 = __expf(s0 - m), e1 = __expf(s1 - m);
            float ss = e0 + e1;
#pragma unroll
            for (int o = 16; o; o >>= 1) ss += __shfl_xor_sync(0xffffffffu, ss, o);
            float inv = 1.f / ss;
            wa0 += e0 * inv;
            wa1 += e1 * inv;
        }
        atomicAdd(&wgt[lane], wa0);
        atomicAdd(&wgt[lane + 32], wa1);
    }
    __syncthreads();

    // ---- xw[j] = sum_k wgt[k] * x[k][j] (hi+lo, swizzled) ----
    {
        float a = 0.f;
#pragma unroll 8
        for (int k = 0; k < 64; k++) {
            uint32_t boff = (uint32_t)(k * 512 + ((2 * tid) ^ ((k & 7) << 4)));
            a += wgt[k] *
                 (__bfloat162float(*(__nv_bfloat16*)(smem + XH_OFF + boff)) +
                  __bfloat162float(*(__nv_bfloat16*)(smem + XL_OFF + boff)));
        }
        xw[tid] = a;
    }
    __syncthreads();

    // ---- xg[g] = bias[g] + sum_j xw[j] * W2[j][g] ----
    if (tid < 128) {
        float a = g_bias[tid];
        const float* Wp = g_W2 + tid;
#pragma unroll 4
        for (int j = 0; j < 256; j++) a += xw[j] * __ldg(Wp + (size_t)j * 128);
        g_xg[(size_t)n * 128 + tid] = a;
    }
}

// ---------------- LSTM scan + critic (R9/R10 version) ----------------
__device__ __forceinline__ float sigmoidf_(float v) { return 1.f / (1.f + __expf(-v)); }

__global__ void __launch_bounds__(128) lstm_kernel(const float* __restrict__ done,
                                                   const float* __restrict__ h0,
                                                   const float* __restrict__ c0,
                                                   const float* __restrict__ whh,
                                                   const float* __restrict__ cw,
                                                   const float* __restrict__ cb,
                                                   float* __restrict__ out) {
    __shared__ float whs[32 * 128];
    const int tid = threadIdx.x, lane = tid & 31, w = tid >> 5;
    const int b = blockIdx.x * 4 + w;
    for (int idx = tid; idx < 4096; idx += 128) {
        int g = idx >> 5, m = idx & 31;
        whs[m * 128 + g] = whh[idx];
    }
    __syncthreads();
    float h = h0[b * H_DIM + lane], c = c0[b * H_DIM + lane];
    const float cwv = cw[lane], cbv = cb[0];

    float dn = done[b];
    const float* xp = g_xg + (size_t)b * 128;
    float pai = xp[lane], paf = xp[32 + lane], pag = xp[64 + lane], pao = xp[96 + lane];

    for (int t = 0; t < T_STEPS; t++) {
        float ai = pai, af = paf, ag = pag, ao = pao, dc = dn;
        if (t < 63) {
            int n2 = (t + 1) * B_ENV + b;
            dn = done[n2];
            const float* x2 = g_xg + (size_t)n2 * 128;
            pai = x2[lane]; paf = x2[32 + lane]; pag = x2[64 + lane]; pao = x2[96 + lane];
        }
        float keep = 1.f - dc;
        h *= keep; c *= keep;
        float hv[32];
#pragma unroll
        for (int m = 0; m < 32; m++) hv[m] = __shfl_sync(0xffffffffu, h, m);
#pragma unroll
        for (int m = 0; m < 32; m++) {
            ai += hv[m] * whs[m * 128 + lane];
            af += hv[m] * whs[m * 128 + 32 + lane];
            ag += hv[m] * whs[m * 128 + 64 + lane];
            ao += hv[m] * whs[m * 128 + 96 + lane];
        }
        float gi = sigmoidf_(ai), gf = sigmoidf_(af), gg = tanhf(ag), go = sigmoidf_(ao);
        c = gf * c + gi * gg;
        h = go * tanhf(c);
        float pv = h * cwv;
#pragma unroll
        for (int o = 16; o; o >>= 1) pv += __shfl_xor_sync(0xffffffffu, pv, o);
        if (lane == 0) out[t * B_ENV + b] = pv + cbv;
    }
}

extern "C" void kernel_launch(void* const* d_in, const int* in_sizes, int n_in,
                              void* d_out, int out_size) {
    const float* x    = (const float*)d_in[0];
    const float* done = (const float*)d_in[1];
    const void*  mask = d_in[2];
    const float* h0   = (const float*)d_in[3];
    const float* c0   = (const float*)d_in[4];
    const float* ipw  = (const float*)d_in[5];
    const float* opw  = (const float*)d_in[6];
    const float* wih  = (const float*)d_in[7];
    const float* whh  = (const float*)d_in[8];
    const float* bih  = (const float*)d_in[9];
    const float* bhh  = (const float*)d_in[10];
    const float* cw   = (const float*)d_in[11];
    const float* cb   = (const float*)d_in[12];
    float*       out  = (float*)d_out;
    (void)in_sizes; (void)n_in; (void)out_size;

    cudaFuncSetAttribute(attn_mma, cudaFuncAttributeMaxDynamicSharedMemorySize, SMEM_SZ);
    prep1<<<128, 256>>>(ipw, opw);
    prep2<<<97, 256>>>(wih, bih, bhh);
    attn_mma<<<N_TOT, 256, SMEM_SZ>>>(x, mask);
    lstm_kernel<<<32, 128>>>(done, h0, c0, whh, cw, cb, out);
}

// round 12
// speedup vs baseline: 1.4529x; 1.2331x over previous
#include <cuda_runtime.h>
#include <cuda_fp16.h>
#include <cstdint>

#define T_STEPS 64
#define B_ENV 128
#define L_TOK 64
#define E_DIM 256
#define H_DIM 32
#define N_TOT (T_STEPS * B_ENV)

__device__ float g_M[65536];
__device__ float g_WeffT[65536];
__device__ float g_W2[32768];
__device__ float g_bias[128];
__device__ unsigned short g_Mt16[65536]; // fp16 of M^T [j][i]
__device__ float g_xg[(size_t)N_TOT * 128];

// ---------------- helpers ----------------
__device__ __forceinline__ uint32_t smem_u32(const void* p) {
    uint32_t a;
    asm("{ .reg .u64 t; cvta.to.shared.u64 t, %1; cvt.u32.u64 %0, t; }" : "=r"(a) : "l"(p));
    return a;
}
__device__ __forceinline__ void ldm4(uint32_t* r, uint32_t a) {
    asm volatile("ldmatrix.sync.aligned.m8n8.x4.shared.b16 {%0,%1,%2,%3}, [%4];"
        : "=r"(r[0]), "=r"(r[1]), "=r"(r[2]), "=r"(r[3]) : "r"(a));
}
__device__ __forceinline__ void mma_fp16(float* d, const uint32_t* a, const uint32_t* b) {
    asm volatile("mma.sync.aligned.m16n8k16.row.col.f32.f16.f16.f32 "
        "{%0,%1,%2,%3}, {%4,%5,%6,%7}, {%8,%9}, {%0,%1,%2,%3};"
        : "+f"(d[0]), "+f"(d[1]), "+f"(d[2]), "+f"(d[3])
        : "r"(a[0]), "r"(a[1]), "r"(a[2]), "r"(a[3]), "r"(b[0]), "r"(b[1]));
}
__device__ __forceinline__ uint32_t pack_h2(__half lo, __half hi) {
    __half2 p = __halves2half2(lo, hi);
    return *(uint32_t*)&p;
}
__device__ __forceinline__ void cp16(uint32_t dst, const void* src) {
    asm volatile("cp.async.cg.shared.global [%0], [%1], 16;" :: "r"(dst), "l"(src));
}
#define CP_COMMIT() asm volatile("cp.async.commit_group;" ::: "memory")
#define CP_WAIT0()  asm volatile("cp.async.wait_group 0;" ::: "memory")

// ---------------- prep1: M (b<64), WeffT (b>=64) ----------------
__global__ void __launch_bounds__(256) prep1(const float* __restrict__ ipw, const float* __restrict__ opw) {
    __shared__ float As[32][33], Bs[32][33];
    const int b = blockIdx.x, tid = threadIdx.x, tx = tid & 31, ty = tid >> 5;
    float acc[4] = {0.f, 0.f, 0.f, 0.f};
    if (b < 64) {
        int i0 = (b >> 3) * 32, j0 = (b & 7) * 32;
        const float *Wq = ipw, *Wk = ipw + 65536;
        for (int e0 = 0; e0 < 256; e0 += 32) {
#pragma unroll
            for (int r = 0; r < 4; r++) {
                int e = ty + 8 * r;
                As[e][tx] = Wq[(e0 + e) * 256 + i0 + tx];
                Bs[e][tx] = Wk[(e0 + e) * 256 + j0 + tx];
            }
            __syncthreads();
#pragma unroll 8
            for (int e = 0; e < 32; e++) {
                float bv = Bs[e][tx];
#pragma unroll
                for (int r = 0; r < 4; r++) acc[r] += As[e][ty + 8 * r] * bv;
            }
            __syncthreads();
        }
#pragma unroll
        for (int r = 0; r < 4; r++) g_M[(i0 + ty + 8 * r) * 256 + j0 + tx] = acc[r];
    } else {
        int t = b - 64, j0 = (t >> 3) * 32, f0 = (t & 7) * 32;
        const float* Wv = ipw + 131072;
        for (int e0 = 0; e0 < 256; e0 += 32) {
#pragma unroll
            for (int r = 0; r < 4; r++) {
                int e = ty + 8 * r;
                As[e][tx] = Wv[(e0 + e) * 256 + j0 + tx];
                Bs[tx][e] = opw[(f0 + e) * 256 + e0 + tx];
            }
            __syncthreads();
#pragma unroll 8
            for (int e = 0; e < 32; e++) {
                float bv = Bs[e][tx];
#pragma unroll
                for (int r = 0; r < 4; r++) acc[r] += As[e][ty + 8 * r] * bv;
            }
            __syncthreads();
        }
#pragma unroll
        for (int r = 0; r < 4; r++) g_WeffT[(j0 + ty + 8 * r) * 256 + f0 + tx] = acc[r];
    }
}

// ---------------- prep2: Mt fp16 (b<64), W2 (64..95), bias (96) --------------
__global__ void __launch_bounds__(256) prep2(const float* __restrict__ wih,
                                             const float* __restrict__ bih,
                                             const float* __restrict__ bhh) {
    __shared__ float As[32][33], Bs[32][33];
    const int b = blockIdx.x, tid = threadIdx.x, tx = tid & 31, ty = tid >> 5;
    if (b < 64) {
        int i0 = (b >> 3) * 32, j0 = (b & 7) * 32;
#pragma unroll
        for (int r = 0; r < 4; r++) As[ty + 8 * r][tx] = g_M[(i0 + ty + 8 * r) * 256 + j0 + tx];
        __syncthreads();
#pragma unroll
        for (int r = 0; r < 4; r++) {
            int jj = ty + 8 * r;
            __half h = __float2half_rn(As[tx][jj]);
            g_Mt16[(j0 + jj) * 256 + i0 + tx] = *(unsigned short*)&h;
        }
        return;
    }
    if (b < 96) {
        int t = b - 64, j0 = (t >> 2) * 32, g0 = (t & 3) * 32;
        float acc[4] = {0.f, 0.f, 0.f, 0.f};
        for (int f0 = 0; f0 < 256; f0 += 32) {
#pragma unroll
            for (int r = 0; r < 4; r++) {
                int e = ty + 8 * r;
                As[tx][e] = g_WeffT[(j0 + e) * 256 + f0 + tx];
                Bs[tx][e] = wih[(g0 + e) * 256 + f0 + tx];
            }
            __syncthreads();
#pragma unroll 8
            for (int f = 0; f < 32; f++) {
                float bv = Bs[f][tx];
#pragma unroll
                for (int r = 0; r < 4; r++) acc[r] += As[f][ty + 8 * r] * bv;
            }
            __syncthreads();
        }
#pragma unroll
        for (int r = 0; r < 4; r++) g_W2[(j0 + ty + 8 * r) * 128 + g0 + tx] = acc[r];
        return;
    }
    if (tid < 128) g_bias[tid] = bih[tid] + bhh[tid];
}

// ---------------- attention: fp16 2-term, 1 sample/CTA, 2 CTAs/SM ------------
#define XH_OFF   0        /* x hi: 64 x 512 */
#define XL_OFF   32768    /* x lo */
#define STG_OFF  65536    /* Mt16 chunk: 64 x 512 */
#define TSH_OFF  98304    /* ts hi: 64 x 128 */
#define TSL_OFF  106496   /* ts lo */
#define SMEM_SZ  114688
#define SC_OFF   STG_OFF           /* f32 [64][68] after GEMMs */
#define DF_OFF   TSH_OFF
#define WGT_OFF  (TSH_OFF + 256)
#define XW_OFF   (TSH_OFF + 512)
#define MODE_OFF (TSH_OFF + 2048)

__global__ void __launch_bounds__(256, 2) attn_mma(const float* __restrict__ x,
                                                   const void* __restrict__ mask) {
    extern __shared__ char smem[];
    const uint32_t sb = smem_u32(smem);
    const int tid = threadIdx.x, lane = tid & 31, w = tid >> 5;
    const int n = blockIdx.x;

    // stage chunk 0 of Mt16
    for (int u = tid; u < 2048; u += 256) {
        int row = u >> 5, c16 = (u & 31) << 4;
        uint32_t d = STG_OFF + row * 512 + (c16 ^ ((row & 7) << 4));
        cp16(sb + d, (const uint4*)g_Mt16 + u);
    }
    CP_COMMIT();

    // load x f32 -> fp16 hi/lo smem (swizzled)
    const float2* xb = (const float2*)(x + (size_t)n * (L_TOK * E_DIM));
    for (int idx = tid; idx < 8192; idx += 256) {
        int r = idx >> 7, cp = idx & 127;
        float2 v = xb[idx];
        __half h0 = __float2half_rn(v.x), h1 = __float2half_rn(v.y);
        __half l0 = __float2half_rn(v.x - __half2float(h0));
        __half l1 = __float2half_rn(v.y - __half2float(h1));
        uint32_t boff = (uint32_t)(r * 512 + ((cp * 4) ^ ((r & 7) << 4)));
        *(uint32_t*)(smem + XH_OFF + boff) = pack_h2(h0, h1);
        *(uint32_t*)(smem + XL_OFF + boff) = pack_h2(l0, l1);
    }
    CP_WAIT0();
    __syncthreads();

    // warp layout: 4x2 grid of m16n32 tiles over 64x64 outputs
    const int mg = w >> 1, ng = w & 1;
    const int arow = mg * 16 + (lane & 15);
    const uint32_t a_rot = (arow & 7) << 4, a_klo = (lane >> 4) << 4;
    const uint32_t axh = sb + XH_OFF + arow * 512;
    const uint32_t axl = sb + XL_OFF + arow * 512;
    const uint32_t ath = sb + TSH_OFF + arow * 128;
    const uint32_t atl = sb + TSL_OFF + arow * 128;
    const int br0 = ng * 32 + (lane & 7) + ((lane & 16) >> 1), br1 = br0 + 16;
    const uint32_t b_rot0 = (br0 & 7) << 4, b_rot1 = (br1 & 7) << 4;
    const uint32_t bklo = ((lane >> 3) & 1) << 4;

    float acc2[4][4];
#pragma unroll
    for (int nt = 0; nt < 4; nt++)
#pragma unroll
        for (int q = 0; q < 4; q++) acc2[nt][q] = 0.f;

    for (int ch = 0; ch < 4; ch++) {
        // GEMM1: ts_ch = (x_hi + x_lo) @ Mt16_ch^T  (K=256)
        float acc1[4][4];
#pragma unroll
        for (int nt = 0; nt < 4; nt++)
#pragma unroll
            for (int q = 0; q < 4; q++) acc1[nt][q] = 0.f;
        const uint32_t sg0 = sb + STG_OFF + br0 * 512, sg1 = sb + STG_OFF + br1 * 512;
#pragma unroll 4
        for (int ks = 0; ks < 16; ks++) {
            uint32_t kb = ks * 32;
            uint32_t Ah[4], Al[4], B0[4], B1[4];
            ldm4(Ah, axh + ((kb + a_klo) ^ a_rot));
            ldm4(Al, axl + ((kb + a_klo) ^ a_rot));
            ldm4(B0, sg0 + ((kb + bklo) ^ b_rot0));
            ldm4(B1, sg1 + ((kb + bklo) ^ b_rot1));
            mma_fp16(acc1[0], Ah, B0); mma_fp16(acc1[1], Ah, B0 + 2);
            mma_fp16(acc1[2], Ah, B1); mma_fp16(acc1[3], Ah, B1 + 2);
            mma_fp16(acc1[0], Al, B0); mma_fp16(acc1[1], Al, B0 + 2);
            mma_fp16(acc1[2], Al, B1); mma_fp16(acc1[3], Al, B1 + 2);
        }
        // write ts chunk (fp16 hi/lo, swizzled 128B rows)
#pragma unroll
        for (int nt = 0; nt < 4; nt++) {
            int col = ng * 32 + nt * 8 + 2 * (lane & 3);
            int r0 = mg * 16 + (lane >> 2);
#pragma unroll
            for (int hh = 0; hh < 2; hh++) {
                int rr = r0 + 8 * hh;
                float v0 = acc1[nt][2 * hh], v1 = acc1[nt][2 * hh + 1];
                __half h0 = __float2half_rn(v0), h1 = __float2half_rn(v1);
                __half l0 = __float2half_rn(v0 - __half2float(h0));
                __half l1 = __float2half_rn(v1 - __half2float(h1));
                uint32_t boff = (uint32_t)(rr * 128 + ((col * 2) ^ ((rr & 7) << 4)));
                *(uint32_t*)(smem + TSH_OFF + boff) = pack_h2(h0, h1);
                *(uint32_t*)(smem + TSL_OFF + boff) = pack_h2(l0, l1);
            }
        }
        __syncthreads();   // ts visible; GEMM1 done reading STG

        // prefetch next Mt16 chunk (overlaps GEMM2)
        if (ch < 3) {
            for (int u = tid; u < 2048; u += 256) {
                int row = u >> 5, c16 = (u & 31) << 4;
                uint32_t d = STG_OFF + row * 512 + (c16 ^ ((row & 7) << 4));
                cp16(sb + d, (const uint4*)(g_Mt16 + (ch + 1) * 16384) + u);
            }
            CP_COMMIT();
        }

        // GEMM2 partial: sc += (ts_hi + ts_lo) @ x_hi_ch^T  (K=64)
        const uint32_t bxh0 = sb + XH_OFF + br0 * 512, bxh1 = sb + XH_OFF + br1 * 512;
#pragma unroll
        for (int ks = 0; ks < 4; ks++) {
            uint32_t kb = ks * 32, xc = ch * 128 + kb + bklo;
            uint32_t Ah[4], Al[4], Bh0[4], Bh1[4];
            ldm4(Ah, ath + ((kb + a_klo) ^ a_rot));
            ldm4(Al, atl + ((kb + a_klo) ^ a_rot));
            ldm4(Bh0, bxh0 + (xc ^ b_rot0));
            ldm4(Bh1, bxh1 + (xc ^ b_rot1));
            mma_fp16(acc2[0], Ah, Bh0); mma_fp16(acc2[1], Ah, Bh0 + 2);
            mma_fp16(acc2[2], Ah, Bh1); mma_fp16(acc2[3], Ah, Bh1 + 2);
            mma_fp16(acc2[0], Al, Bh0); mma_fp16(acc2[1], Al, Bh0 + 2);
            mma_fp16(acc2[2], Al, Bh1); mma_fp16(acc2[3], Al, Bh1 + 2);
        }
        if (ch < 3) { CP_WAIT0(); }
        __syncthreads();
    }

    // ---- write sc (overlay STG), scaled; warp 0 detects mask dtype ----
    float* scp = (float*)(smem + SC_OFF);
#pragma unroll
    for (int nt = 0; nt < 4; nt++) {
        int col = ng * 32 + nt * 8 + 2 * (lane & 3);
        int r0 = mg * 16 + (lane >> 2);
        scp[r0 * 68 + col]           = acc2[nt][0] * 0.0625f;
        scp[r0 * 68 + col + 1]       = acc2[nt][1] * 0.0625f;
        scp[(r0 + 8) * 68 + col]     = acc2[nt][2] * 0.0625f;
        scp[(r0 + 8) * 68 + col + 1] = acc2[nt][3] * 0.0625f;
    }
    if (w == 0) {
        const unsigned* mw = (const unsigned*)mask;
        int f = 0, g = 0;
        for (int i = lane; i < 2048; i += 32) {
            unsigned v = mw[i];
            f |= (v == 0x3F800000u);
            g |= (v > 1u);
        }
        f = __any_sync(0xffffffffu, f);
        g = __any_sync(0xffffffffu, g);
        if (!lane) *(int*)(smem + MODE_OFF) = f ? 2 : (g ? 1 : 0);
    }
    __syncthreads();

    // ---- dropped flags + wgt init ----
    float* dfp = (float*)(smem + DF_OFF);
    float* wgt = (float*)(smem + WGT_OFF);
    float* xw  = (float*)(smem + XW_OFF);
    if (tid < 64) {
        int mode = *(int*)(smem + MODE_OFF);
        size_t mi = (size_t)n * 64 + tid;
        bool at;
        if (mode == 0)      at = ((const int*)mask)[mi] != 0;
        else if (mode == 1) at = ((const uint8_t*)mask)[mi] != 0;
        else                at = ((const float*)mask)[mi] != 0.f;
        dfp[tid] = at ? 0.f : 1.f;
        wgt[tid] = 0.f;
    }
    __syncthreads();

    // ---- softmax: 8 rows/warp ----
    {
        const bool dk0 = dfp[lane] > 0.5f, dk1 = dfp[lane + 32] > 0.5f;
        float wa0 = 0.f, wa1 = 0.f;
#pragma unroll
        for (int r = 0; r < 8; r++) {
            int lq = w * 8 + r;
            bool dq = dfp[lq] > 0.5f;
            float s0 = scp[lq * 68 + lane], s1 = scp[lq * 68 + lane + 32];
            if (dq && dk0) s0 = -1e30f;
            if (dq && dk1) s1 = -1e30f;
            float m = fmaxf(s0, s1);
#pragma unroll
            for (int o = 16; o; o >>= 1) m = fmaxf(m, __shfl_xor_sync(0xffffffffu, m, o));
            float e0 = __expf(s0 - m), e1 = __expf(s1 - m);
            float ss = e0 + e1;
#pragma unroll
            for (int o = 16; o; o >>= 1) ss += __shfl_xor_sync(0xffffffffu, ss, o);
            float inv = 1.f / ss;
            wa0 += e0 * inv;
            wa1 += e1 * inv;
        }
        atomicAdd(&wgt[lane], wa0);
        atomicAdd(&wgt[lane + 32], wa1);
    }
    __syncthreads();

    // ---- xw[j] = sum_k wgt[k] * x[k][j] (hi+lo, swizzled) ----
    {
        float a = 0.f;
#pragma unroll 8
        for (int k = 0; k < 64; k++) {
            uint32_t boff = (uint32_t)(k * 512 + ((2 * tid) ^ ((k & 7) << 4)));
            a += wgt[k] *
                 (__half2float(*(__half*)(smem + XH_OFF + boff)) +
                  __half2float(*(__half*)(smem + XL_OFF + boff)));
        }
        xw[tid] = a;
    }
    __syncthreads();

    // ---- xg[g] = bias[g] + sum_j xw[j] * W2[j][g] ----
    if (tid < 128) {
        float a = g_bias[tid];
        const float* Wp = g_W2 + tid;
#pragma unroll 4
        for (int j = 0; j < 256; j++) a += xw[j] * __ldg(Wp + (size_t)j * 128);
        g_xg[(size_t)n * 128 + tid] = a;
    }
}

// ---------------- LSTM scan + critic (R9/R10 version) ----------------
__device__ __forceinline__ float sigmoidf_(float v) { return 1.f / (1.f + __expf(-v)); }

__global__ void __launch_bounds__(128) lstm_kernel(const float* __restrict__ done,
                                                   const float* __restrict__ h0,
                                                   const float* __restrict__ c0,
                                                   const float* __restrict__ whh,
                                                   const float* __restrict__ cw,
                                                   const float* __restrict__ cb,
                                                   float* __restrict__ out) {
    __shared__ float whs[32 * 128];
    const int tid = threadIdx.x, lane = tid & 31, w = tid >> 5;
    const int b = blockIdx.x * 4 + w;
    for (int idx = tid; idx < 4096; idx += 128) {
        int g = idx >> 5, m = idx & 31;
        whs[m * 128 + g] = whh[idx];
    }
    __syncthreads();
    float h = h0[b * H_DIM + lane], c = c0[b * H_DIM + lane];
    const float cwv = cw[lane], cbv = cb[0];

    float dn = done[b];
    const float* xp = g_xg + (size_t)b * 128;
    float pai = xp[lane], paf = xp[32 + lane], pag = xp[64 + lane], pao = xp[96 + lane];

    for (int t = 0; t < T_STEPS; t++) {
        float ai = pai, af = paf, ag = pag, ao = pao, dc = dn;
        if (t < 63) {
            int n2 = (t + 1) * B_ENV + b;
            dn = done[n2];
            const float* x2 = g_xg + (size_t)n2 * 128;
            pai = x2[lane]; paf = x2[32 + lane]; pag = x2[64 + lane]; pao = x2[96 + lane];
        }
        float keep = 1.f - dc;
        h *= keep; c *= keep;
        float hv[32];
#pragma unroll
        for (int m = 0; m < 32; m++) hv[m] = __shfl_sync(0xffffffffu, h, m);
#pragma unroll
        for (int m = 0; m < 32; m++) {
            ai += hv[m] * whs[m * 128 + lane];
            af += hv[m] * whs[m * 128 + 32 + lane];
            ag += hv[m] * whs[m * 128 + 64 + lane];
            ao += hv[m] * whs[m * 128 + 96 + lane];
        }
        float gi = sigmoidf_(ai), gf = sigmoidf_(af), gg = tanhf(ag), go = sigmoidf_(ao);
        c = gf * c + gi * gg;
        h = go * tanhf(c);
        float pv = h * cwv;
#pragma unroll
        for (int o = 16; o; o >>= 1) pv += __shfl_xor_sync(0xffffffffu, pv, o);
        if (lane == 0) out[t * B_ENV + b] = pv + cbv;
    }
}

extern "C" void kernel_launch(void* const* d_in, const int* in_sizes, int n_in,
                              void* d_out, int out_size) {
    const float* x    = (const float*)d_in[0];
    const float* done = (const float*)d_in[1];
    const void*  mask = d_in[2];
    const float* h0   = (const float*)d_in[3];
    const float* c0   = (const float*)d_in[4];
    const float* ipw  = (const float*)d_in[5];
    const float* opw  = (const float*)d_in[6];
    const float* wih  = (const float*)d_in[7];
    const float* whh  = (const float*)d_in[8];
    const float* bih  = (const float*)d_in[9];
    const float* bhh  = (const float*)d_in[10];
    const float* cw   = (const float*)d_in[11];
    const float* cb   = (const float*)d_in[12];
    float*       out  = (float*)d_out;
    (void)in_sizes; (void)n_in; (void)out_size;

    cudaFuncSetAttribute(attn_mma, cudaFuncAttributeMaxDynamicSharedMemorySize, SMEM_SZ);
    prep1<<<128, 256>>>(ipw, opw);
    prep2<<<97, 256>>>(wih, bih, bhh);
    attn_mma<<<N_TOT, 256, SMEM_SZ>>>(x, mask);
    lstm_kernel<<<32, 128>>>(done, h0, c0, whh, cw, cb, out);
}

// round 13
// speedup vs baseline: 2.0199x; 1.3902x over previous
#include <cuda_runtime.h>
#include <cuda_fp16.h>
#include <cstdint>

#define T_STEPS 64
#define B_ENV 128
#define L_TOK 64
#define E_DIM 256
#define H_DIM 32
#define N_TOT (T_STEPS * B_ENV)

__device__ float g_M[65536];
__device__ float g_WeffT[65536];
__device__ float g_W2[32768];
__device__ float g_bias[128];
__device__ unsigned short g_Mt16[65536]; // fp16 of M^T [j][i]
__device__ float g_xg[(size_t)N_TOT * 128];

// ---------------- helpers ----------------
__device__ __forceinline__ uint32_t smem_u32(const void* p) {
    uint32_t a;
    asm("{ .reg .u64 t; cvta.to.shared.u64 t, %1; cvt.u32.u64 %0, t; }" : "=r"(a) : "l"(p));
    return a;
}
__device__ __forceinline__ void ldm4(uint32_t* r, uint32_t a) {
    asm volatile("ldmatrix.sync.aligned.m8n8.x4.shared.b16 {%0,%1,%2,%3}, [%4];"
        : "=r"(r[0]), "=r"(r[1]), "=r"(r[2]), "=r"(r[3]) : "r"(a));
}
__device__ __forceinline__ void mma_fp16(float* d, const uint32_t* a, const uint32_t* b) {
    asm volatile("mma.sync.aligned.m16n8k16.row.col.f32.f16.f16.f32 "
        "{%0,%1,%2,%3}, {%4,%5,%6,%7}, {%8,%9}, {%0,%1,%2,%3};"
        : "+f"(d[0]), "+f"(d[1]), "+f"(d[2]), "+f"(d[3])
        : "r"(a[0]), "r"(a[1]), "r"(a[2]), "r"(a[3]), "r"(b[0]), "r"(b[1]));
}
__device__ __forceinline__ uint32_t pack_h2(__half lo, __half hi) {
    __half2 p = __halves2half2(lo, hi);
    return *(uint32_t*)&p;
}
__device__ __forceinline__ void cp16(uint32_t dst, const void* src) {
    asm volatile("cp.async.cg.shared.global [%0], [%1], 16;" :: "r"(dst), "l"(src));
}
#define CP_COMMIT() asm volatile("cp.async.commit_group;" ::: "memory")
#define CP_WAIT0()  asm volatile("cp.async.wait_group 0;" ::: "memory")

// ---------------- prep1: M (b<64), WeffT (b>=64) ----------------
__global__ void __launch_bounds__(256) prep1(const float* __restrict__ ipw, const float* __restrict__ opw) {
    __shared__ float As[32][33], Bs[32][33];
    const int b = blockIdx.x, tid = threadIdx.x, tx = tid & 31, ty = tid >> 5;
    float acc[4] = {0.f, 0.f, 0.f, 0.f};
    if (b < 64) {
        int i0 = (b >> 3) * 32, j0 = (b & 7) * 32;
        const float *Wq = ipw, *Wk = ipw + 65536;
        for (int e0 = 0; e0 < 256; e0 += 32) {
#pragma unroll
            for (int r = 0; r < 4; r++) {
                int e = ty + 8 * r;
                As[e][tx] = Wq[(e0 + e) * 256 + i0 + tx];
                Bs[e][tx] = Wk[(e0 + e) * 256 + j0 + tx];
            }
            __syncthreads();
#pragma unroll 8
            for (int e = 0; e < 32; e++) {
                float bv = Bs[e][tx];
#pragma unroll
                for (int r = 0; r < 4; r++) acc[r] += As[e][ty + 8 * r] * bv;
            }
            __syncthreads();
        }
#pragma unroll
        for (int r = 0; r < 4; r++) g_M[(i0 + ty + 8 * r) * 256 + j0 + tx] = acc[r];
    } else {
        int t = b - 64, j0 = (t >> 3) * 32, f0 = (t & 7) * 32;
        const float* Wv = ipw + 131072;
        for (int e0 = 0; e0 < 256; e0 += 32) {
#pragma unroll
            for (int r = 0; r < 4; r++) {
                int e = ty + 8 * r;
                As[e][tx] = Wv[(e0 + e) * 256 + j0 + tx];
                Bs[tx][e] = opw[(f0 + e) * 256 + e0 + tx];
            }
            __syncthreads();
#pragma unroll 8
            for (int e = 0; e < 32; e++) {
                float bv = Bs[e][tx];
#pragma unroll
                for (int r = 0; r < 4; r++) acc[r] += As[e][ty + 8 * r] * bv;
            }
            __syncthreads();
        }
#pragma unroll
        for (int r = 0; r < 4; r++) g_WeffT[(j0 + ty + 8 * r) * 256 + f0 + tx] = acc[r];
    }
}

// ---------------- prep2: Mt fp16 (b<64), W2 (64..95), bias (96) --------------
__global__ void __launch_bounds__(256) prep2(const float* __restrict__ wih,
                                             const float* __restrict__ bih,
                                             const float* __restrict__ bhh) {
    __shared__ float As[32][33], Bs[32][33];
    const int b = blockIdx.x, tid = threadIdx.x, tx = tid & 31, ty = tid >> 5;
    if (b < 64) {
        int i0 = (b >> 3) * 32, j0 = (b & 7) * 32;
#pragma unroll
        for (int r = 0; r < 4; r++) As[ty + 8 * r][tx] = g_M[(i0 + ty + 8 * r) * 256 + j0 + tx];
        __syncthreads();
#pragma unroll
        for (int r = 0; r < 4; r++) {
            int jj = ty + 8 * r;
            __half h = __float2half_rn(As[tx][jj]);
            g_Mt16[(j0 + jj) * 256 + i0 + tx] = *(unsigned short*)&h;
        }
        return;
    }
    if (b < 96) {
        int t = b - 64, j0 = (t >> 2) * 32, g0 = (t & 3) * 32;
        float acc[4] = {0.f, 0.f, 0.f, 0.f};
        for (int f0 = 0; f0 < 256; f0 += 32) {
#pragma unroll
            for (int r = 0; r < 4; r++) {
                int e = ty + 8 * r;
                As[tx][e] = g_WeffT[(j0 + e) * 256 + f0 + tx];
                Bs[tx][e] = wih[(g0 + e) * 256 + f0 + tx];
            }
            __syncthreads();
#pragma unroll 8
            for (int f = 0; f < 32; f++) {
                float bv = Bs[f][tx];
#pragma unroll
                for (int r = 0; r < 4; r++) acc[r] += As[f][ty + 8 * r] * bv;
            }
            __syncthreads();
        }
#pragma unroll
        for (int r = 0; r < 4; r++) g_W2[(j0 + ty + 8 * r) * 128 + g0 + tx] = acc[r];
        return;
    }
    if (tid < 128) g_bias[tid] = bih[tid] + bhh[tid];
}

// ---------------- attention: full fp16, 1 sample/CTA, 3 CTAs/SM --------------
#define XH_OFF   0        /* x fp16: 64 x 512 */
#define STG_OFF  32768    /* Mt16 chunk: 64 x 512 */
#define TSH_OFF  65536    /* ts fp16: 64 x 128 */
#define SMEM_SZ  73728
#define SC_OFF   STG_OFF           /* f32 [64][68] = 17408 after GEMMs */
#define DF_OFF   TSH_OFF
#define WGT_OFF  (TSH_OFF + 256)
#define XW_OFF   (TSH_OFF + 512)
#define MODE_OFF (TSH_OFF + 2048)

__global__ void __launch_bounds__(256, 3) attn_mma(const float* __restrict__ x,
                                                   const void* __restrict__ mask) {
    extern __shared__ char smem[];
    const uint32_t sb = smem_u32(smem);
    const int tid = threadIdx.x, lane = tid & 31, w = tid >> 5;
    const int n = blockIdx.x;

    // stage chunk 0 of Mt16
    for (int u = tid; u < 2048; u += 256) {
        int row = u >> 5, c16 = (u & 31) << 4;
        uint32_t d = STG_OFF + row * 512 + (c16 ^ ((row & 7) << 4));
        cp16(sb + d, (const uint4*)g_Mt16 + u);
    }
    CP_COMMIT();

    // load x f32 -> fp16 smem (swizzled)
    const float2* xb = (const float2*)(x + (size_t)n * (L_TOK * E_DIM));
    for (int idx = tid; idx < 8192; idx += 256) {
        int r = idx >> 7, cp = idx & 127;
        float2 v = xb[idx];
        uint32_t boff = (uint32_t)(r * 512 + ((cp * 4) ^ ((r & 7) << 4)));
        *(uint32_t*)(smem + XH_OFF + boff) =
            pack_h2(__float2half_rn(v.x), __float2half_rn(v.y));
    }
    CP_WAIT0();
    __syncthreads();

    // warp layout: 4x2 grid of m16n32 tiles over 64x64 outputs
    const int mg = w >> 1, ng = w & 1;
    const int arow = mg * 16 + (lane & 15);
    const uint32_t a_rot = (arow & 7) << 4, a_klo = (lane >> 4) << 4;
    const uint32_t axh = sb + XH_OFF + arow * 512;
    const uint32_t ath = sb + TSH_OFF + arow * 128;
    const int br0 = ng * 32 + (lane & 7) + ((lane & 16) >> 1), br1 = br0 + 16;
    const uint32_t b_rot0 = (br0 & 7) << 4, b_rot1 = (br1 & 7) << 4;
    const uint32_t bklo = ((lane >> 3) & 1) << 4;

    float acc2[4][4];
#pragma unroll
    for (int nt = 0; nt < 4; nt++)
#pragma unroll
        for (int q = 0; q < 4; q++) acc2[nt][q] = 0.f;

    for (int ch = 0; ch < 4; ch++) {
        // GEMM1: ts_ch = x @ Mt16_ch^T  (K=256, single term)
        float acc1[4][4];
#pragma unroll
        for (int nt = 0; nt < 4; nt++)
#pragma unroll
            for (int q = 0; q < 4; q++) acc1[nt][q] = 0.f;
        const uint32_t sg0 = sb + STG_OFF + br0 * 512, sg1 = sb + STG_OFF + br1 * 512;
#pragma unroll 4
        for (int ks = 0; ks < 16; ks++) {
            uint32_t kb = ks * 32;
            uint32_t Ah[4], B0[4], B1[4];
            ldm4(Ah, axh + ((kb + a_klo) ^ a_rot));
            ldm4(B0, sg0 + ((kb + bklo) ^ b_rot0));
            ldm4(B1, sg1 + ((kb + bklo) ^ b_rot1));
            mma_fp16(acc1[0], Ah, B0); mma_fp16(acc1[1], Ah, B0 + 2);
            mma_fp16(acc1[2], Ah, B1); mma_fp16(acc1[3], Ah, B1 + 2);
        }
        // write ts chunk (fp16, swizzled 128B rows)
#pragma unroll
        for (int nt = 0; nt < 4; nt++) {
            int col = ng * 32 + nt * 8 + 2 * (lane & 3);
            int r0 = mg * 16 + (lane >> 2);
#pragma unroll
            for (int hh = 0; hh < 2; hh++) {
                int rr = r0 + 8 * hh;
                uint32_t boff = (uint32_t)(rr * 128 + ((col * 2) ^ ((rr & 7) << 4)));
                *(uint32_t*)(smem + TSH_OFF + boff) =
                    pack_h2(__float2half_rn(acc1[nt][2 * hh]),
                            __float2half_rn(acc1[nt][2 * hh + 1]));
            }
        }
        __syncthreads();   // ts visible; GEMM1 done reading STG

        // prefetch next Mt16 chunk (overlaps GEMM2)
        if (ch < 3) {
            for (int u = tid; u < 2048; u += 256) {
                int row = u >> 5, c16 = (u & 31) << 4;
                uint32_t d = STG_OFF + row * 512 + (c16 ^ ((row & 7) << 4));
                cp16(sb + d, (const uint4*)(g_Mt16 + (ch + 1) * 16384) + u);
            }
            CP_COMMIT();
        }

        // GEMM2 partial: sc += ts_ch @ x_ch^T  (K=64, single term)
        const uint32_t bxh0 = sb + XH_OFF + br0 * 512, bxh1 = sb + XH_OFF + br1 * 512;
#pragma unroll
        for (int ks = 0; ks < 4; ks++) {
            uint32_t kb = ks * 32, xc = ch * 128 + kb + bklo;
            uint32_t Ah[4], Bh0[4], Bh1[4];
            ldm4(Ah, ath + ((kb + a_klo) ^ a_rot));
            ldm4(Bh0, bxh0 + (xc ^ b_rot0));
            ldm4(Bh1, bxh1 + (xc ^ b_rot1));
            mma_fp16(acc2[0], Ah, Bh0); mma_fp16(acc2[1], Ah, Bh0 + 2);
            mma_fp16(acc2[2], Ah, Bh1); mma_fp16(acc2[3], Ah, Bh1 + 2);
        }
        if (ch < 3) { CP_WAIT0(); }
        __syncthreads();
    }

    // ---- write sc (overlay STG), scaled; warp 0 detects mask dtype ----
    float* scp = (float*)(smem + SC_OFF);
#pragma unroll
    for (int nt = 0; nt < 4; nt++) {
        int col = ng * 32 + nt * 8 + 2 * (lane & 3);
        int r0 = mg * 16 + (lane >> 2);
        scp[r0 * 68 + col]           = acc2[nt][0] * 0.0625f;
        scp[r0 * 68 + col + 1]       = acc2[nt][1] * 0.0625f;
        scp[(r0 + 8) * 68 + col]     = acc2[nt][2] * 0.0625f;
        scp[(r0 + 8) * 68 + col + 1] = acc2[nt][3] * 0.0625f;
    }
    if (w == 0) {
        const unsigned* mw = (const unsigned*)mask;
        int f = 0, g = 0;
        for (int i = lane; i < 2048; i += 32) {
            unsigned v = mw[i];
            f |= (v == 0x3F800000u);
            g |= (v > 1u);
        }
        f = __any_sync(0xffffffffu, f);
        g = __any_sync(0xffffffffu, g);
        if (!lane) *(int*)(smem + MODE_OFF) = f ? 2 : (g ? 1 : 0);
    }
    __syncthreads();

    // ---- dropped flags + wgt init ----
    float* dfp = (float*)(smem + DF_OFF);
    float* wgt = (float*)(smem + WGT_OFF);
    float* xw  = (float*)(smem + XW_OFF);
    if (tid < 64) {
        int mode = *(int*)(smem + MODE_OFF);
        size_t mi = (size_t)n * 64 + tid;
        bool at;
        if (mode == 0)      at = ((const int*)mask)[mi] != 0;
        else if (mode == 1) at = ((const uint8_t*)mask)[mi] != 0;
        else                at = ((const float*)mask)[mi] != 0.f;
        dfp[tid] = at ? 0.f : 1.f;
        wgt[tid] = 0.f;
    }
    __syncthreads();

    // ---- softmax: 8 rows/warp ----
    {
        const bool dk0 = dfp[lane] > 0.5f, dk1 = dfp[lane + 32] > 0.5f;
        float wa0 = 0.f, wa1 = 0.f;
#pragma unroll
        for (int r = 0; r < 8; r++) {
            int lq = w * 8 + r;
            bool dq = dfp[lq] > 0.5f;
            float s0 = scp[lq * 68 + lane], s1 = scp[lq * 68 + lane + 32];
            if (dq && dk0) s0 = -1e30f;
            if (dq && dk1) s1 = -1e30f;
            float m = fmaxf(s0, s1);
#pragma unroll
            for (int o = 16; o; o >>= 1) m = fmaxf(m, __shfl_xor_sync(0xffffffffu, m, o));
            float e0 = __expf(s0 - m), e1 = __expf(s1 - m);
            float ss = e0 + e1;
#pragma unroll
            for (int o = 16; o; o >>= 1) ss += __shfl_xor_sync(0xffffffffu, ss, o);
            float inv = 1.f / ss;
            wa0 += e0 * inv;
            wa1 += e1 * inv;
        }
        atomicAdd(&wgt[lane], wa0);
        atomicAdd(&wgt[lane + 32], wa1);
    }
    __syncthreads();

    // ---- xw[j] = sum_k wgt[k] * x[k][j] (fp16 x, swizzled) ----
    {
        float a = 0.f;
#pragma unroll 8
        for (int k = 0; k < 64; k++) {
            uint32_t boff = (uint32_t)(k * 512 + ((2 * tid) ^ ((k & 7) << 4)));
            a += wgt[k] * __half2float(*(__half*)(smem + XH_OFF + boff));
        }
        xw[tid] = a;
    }
    __syncthreads();

    // ---- xg[g] = bias[g] + sum_j xw[j] * W2[j][g] ----
    if (tid < 128) {
        float a = g_bias[tid];
        const float* Wp = g_W2 + tid;
#pragma unroll 4
        for (int j = 0; j < 256; j++) a += xw[j] * __ldg(Wp + (size_t)j * 128);
        g_xg[(size_t)n * 128 + tid] = a;
    }
}

// ---------------- LSTM scan + critic (R9/R10 version) ----------------
__device__ __forceinline__ float sigmoidf_(float v) { return 1.f / (1.f + __expf(-v)); }

__global__ void __launch_bounds__(128) lstm_kernel(const float* __restrict__ done,
                                                   const float* __restrict__ h0,
                                                   const float* __restrict__ c0,
                                                   const float* __restrict__ whh,
                                                   const float* __restrict__ cw,
                                                   const float* __restrict__ cb,
                                                   float* __restrict__ out) {
    __shared__ float whs[32 * 128];
    const int tid = threadIdx.x, lane = tid & 31, w = tid >> 5;
    const int b = blockIdx.x * 4 + w;
    for (int idx = tid; idx < 4096; idx += 128) {
        int g = idx >> 5, m = idx & 31;
        whs[m * 128 + g] = whh[idx];
    }
    __syncthreads();
    float h = h0[b * H_DIM + lane], c = c0[b * H_DIM + lane];
    const float cwv = cw[lane], cbv = cb[0];

    float dn = done[b];
    const float* xp = g_xg + (size_t)b * 128;
    float pai = xp[lane], paf = xp[32 + lane], pag = xp[64 + lane], pao = xp[96 + lane];

    for (int t = 0; t < T_STEPS; t++) {
        float ai = pai, af = paf, ag = pag, ao = pao, dc = dn;
        if (t < 63) {
            int n2 = (t + 1) * B_ENV + b;
            dn = done[n2];
            const float* x2 = g_xg + (size_t)n2 * 128;
            pai = x2[lane]; paf = x2[32 + lane]; pag = x2[64 + lane]; pao = x2[96 + lane];
        }
        float keep = 1.f - dc;
        h *= keep; c *= keep;
        float hv[32];
#pragma unroll
        for (int m = 0; m < 32; m++) hv[m] = __shfl_sync(0xffffffffu, h, m);
#pragma unroll
        for (int m = 0; m < 32; m++) {
            ai += hv[m] * whs[m * 128 + lane];
            af += hv[m] * whs[m * 128 + 32 + lane];
            ag += hv[m] * whs[m * 128 + 64 + lane];
            ao += hv[m] * whs[m * 128 + 96 + lane];
        }
        float gi = sigmoidf_(ai), gf = sigmoidf_(af), gg = tanhf(ag), go = sigmoidf_(ao);
        c = gf * c + gi * gg;
        h = go * tanhf(c);
        float pv = h * cwv;
#pragma unroll
        for (int o = 16; o; o >>= 1) pv += __shfl_xor_sync(0xffffffffu, pv, o);
        if (lane == 0) out[t * B_ENV + b] = pv + cbv;
    }
}

extern "C" void kernel_launch(void* const* d_in, const int* in_sizes, int n_in,
                              void* d_out, int out_size) {
    const float* x    = (const float*)d_in[0];
    const float* done = (const float*)d_in[1];
    const void*  mask = d_in[2];
    const float* h0   = (const float*)d_in[3];
    const float* c0   = (const float*)d_in[4];
    const float* ipw  = (const float*)d_in[5];
    const float* opw  = (const float*)d_in[6];
    const float* wih  = (const float*)d_in[7];
    const float* whh  = (const float*)d_in[8];
    const float* bih  = (const float*)d_in[9];
    const float* bhh  = (const float*)d_in[10];
    const float* cw   = (const float*)d_in[11];
    const float* cb   = (const float*)d_in[12];
    float*       out  = (float*)d_out;
    (void)in_sizes; (void)n_in; (void)out_size;

    cudaFuncSetAttribute(attn_mma, cudaFuncAttributeMaxDynamicSharedMemorySize, SMEM_SZ);
    prep1<<<128, 256>>>(ipw, opw);
    prep2<<<97, 256>>>(wih, bih, bhh);
    attn_mma<<<N_TOT, 256, SMEM_SZ>>>(x, mask);
    lstm_kernel<<<32, 128>>>(done, h0, c0, whh, cw, cb, out);
}

// round 14
// speedup vs baseline: 2.6238x; 1.2990x over previous
#include <cuda_runtime.h>
#include <cuda_fp16.h>
#include <cstdint>

#define T_STEPS 64
#define B_ENV 128
#define L_TOK 64
#define E_DIM 256
#define H_DIM 32
#define N_TOT (T_STEPS * B_ENV)

__device__ float g_M[65536];
__device__ float g_WeffT[65536];
__device__ float g_W2[32768];
__device__ float g_bias[128];
__device__ unsigned short g_Mt16[65536]; // fp16 of M^T [j][i]
__device__ float g_xg[(size_t)N_TOT * 128];
__device__ int g_mode;                   // mask dtype: 0=int32 1=uint8 2=float32

// ---------------- helpers ----------------
__device__ __forceinline__ uint32_t smem_u32(const void* p) {
    uint32_t a;
    asm("{ .reg .u64 t; cvta.to.shared.u64 t, %1; cvt.u32.u64 %0, t; }" : "=r"(a) : "l"(p));
    return a;
}
__device__ __forceinline__ void ldm4(uint32_t* r, uint32_t a) {
    asm volatile("ldmatrix.sync.aligned.m8n8.x4.shared.b16 {%0,%1,%2,%3}, [%4];"
        : "=r"(r[0]), "=r"(r[1]), "=r"(r[2]), "=r"(r[3]) : "r"(a));
}
__device__ __forceinline__ void mma_fp16(float* d, const uint32_t* a, const uint32_t* b) {
    asm volatile("mma.sync.aligned.m16n8k16.row.col.f32.f16.f16.f32 "
        "{%0,%1,%2,%3}, {%4,%5,%6,%7}, {%8,%9}, {%0,%1,%2,%3};"
        : "+f"(d[0]), "+f"(d[1]), "+f"(d[2]), "+f"(d[3])
        : "r"(a[0]), "r"(a[1]), "r"(a[2]), "r"(a[3]), "r"(b[0]), "r"(b[1]));
}
__device__ __forceinline__ uint32_t pack_h2(__half lo, __half hi) {
    __half2 p = __halves2half2(lo, hi);
    return *(uint32_t*)&p;
}
__device__ __forceinline__ void cp16(uint32_t dst, const void* src) {
    asm volatile("cp.async.cg.shared.global [%0], [%1], 16;" :: "r"(dst), "l"(src));
}
#define CP_COMMIT() asm volatile("cp.async.commit_group;" ::: "memory")
#define CP_WAIT0()  asm volatile("cp.async.wait_group 0;" ::: "memory")

// ---------------- prep1: M (b<64), WeffT (b>=64) ----------------
__global__ void __launch_bounds__(256) prep1(const float* __restrict__ ipw, const float* __restrict__ opw) {
    __shared__ float As[32][33], Bs[32][33];
    const int b = blockIdx.x, tid = threadIdx.x, tx = tid & 31, ty = tid >> 5;
    float acc[4] = {0.f, 0.f, 0.f, 0.f};
    if (b < 64) {
        int i0 = (b >> 3) * 32, j0 = (b & 7) * 32;
        const float *Wq = ipw, *Wk = ipw + 65536;
        for (int e0 = 0; e0 < 256; e0 += 32) {
#pragma unroll
            for (int r = 0; r < 4; r++) {
                int e = ty + 8 * r;
                As[e][tx] = Wq[(e0 + e) * 256 + i0 + tx];
                Bs[e][tx] = Wk[(e0 + e) * 256 + j0 + tx];
            }
            __syncthreads();
#pragma unroll 8
            for (int e = 0; e < 32; e++) {
                float bv = Bs[e][tx];
#pragma unroll
                for (int r = 0; r < 4; r++) acc[r] += As[e][ty + 8 * r] * bv;
            }
            __syncthreads();
        }
#pragma unroll
        for (int r = 0; r < 4; r++) g_M[(i0 + ty + 8 * r) * 256 + j0 + tx] = acc[r];
    } else {
        int t = b - 64, j0 = (t >> 3) * 32, f0 = (t & 7) * 32;
        const float* Wv = ipw + 131072;
        for (int e0 = 0; e0 < 256; e0 += 32) {
#pragma unroll
            for (int r = 0; r < 4; r++) {
                int e = ty + 8 * r;
                As[e][tx] = Wv[(e0 + e) * 256 + j0 + tx];
                Bs[tx][e] = opw[(f0 + e) * 256 + e0 + tx];
            }
            __syncthreads();
#pragma unroll 8
            for (int e = 0; e < 32; e++) {
                float bv = Bs[e][tx];
#pragma unroll
                for (int r = 0; r < 4; r++) acc[r] += As[e][ty + 8 * r] * bv;
            }
            __syncthreads();
        }
#pragma unroll
        for (int r = 0; r < 4; r++) g_WeffT[(j0 + ty + 8 * r) * 256 + f0 + tx] = acc[r];
    }
}

// ------- prep2: Mt fp16 (b<64), W2 (64..95), bias + mask-mode (96) -------
__global__ void __launch_bounds__(256) prep2(const float* __restrict__ wih,
                                             const float* __restrict__ bih,
                                             const float* __restrict__ bhh,
                                             const void* __restrict__ mask) {
    __shared__ float As[32][33], Bs[32][33];
    const int b = blockIdx.x, tid = threadIdx.x, tx = tid & 31, ty = tid >> 5;
    if (b < 64) {
        int i0 = (b >> 3) * 32, j0 = (b & 7) * 32;
#pragma unroll
        for (int r = 0; r < 4; r++) As[ty + 8 * r][tx] = g_M[(i0 + ty + 8 * r) * 256 + j0 + tx];
        __syncthreads();
#pragma unroll
        for (int r = 0; r < 4; r++) {
            int jj = ty + 8 * r;
            __half h = __float2half_rn(As[tx][jj]);
            g_Mt16[(j0 + jj) * 256 + i0 + tx] = *(unsigned short*)&h;
        }
        return;
    }
    if (b < 96) {
        int t = b - 64, j0 = (t >> 2) * 32, g0 = (t & 3) * 32;
        float acc[4] = {0.f, 0.f, 0.f, 0.f};
        for (int f0 = 0; f0 < 256; f0 += 32) {
#pragma unroll
            for (int r = 0; r < 4; r++) {
                int e = ty + 8 * r;
                As[tx][e] = g_WeffT[(j0 + e) * 256 + f0 + tx];
                Bs[tx][e] = wih[(g0 + e) * 256 + f0 + tx];
            }
            __syncthreads();
#pragma unroll 8
            for (int f = 0; f < 32; f++) {
                float bv = Bs[f][tx];
#pragma unroll
                for (int r = 0; r < 4; r++) acc[r] += As[f][ty + 8 * r] * bv;
            }
            __syncthreads();
        }
#pragma unroll
        for (int r = 0; r < 4; r++) g_W2[(j0 + ty + 8 * r) * 128 + g0 + tx] = acc[r];
        return;
    }
    // block 96: bias + mask dtype detection
    if (tid < 128) g_bias[tid] = bih[tid] + bhh[tid];
    __shared__ int sf, sg;
    if (!tid) { sf = 0; sg = 0; }
    __syncthreads();
    const unsigned* mw = (const unsigned*)mask;
    int f = 0, g = 0;
    for (int i = tid; i < 4096; i += 256) {
        unsigned v = mw[i];
        if (v == 0x3F800000u) f = 1;
        if (v > 1u) g = 1;
    }
    if (f) atomicOr(&sf, 1);
    if (g) atomicOr(&sg, 1);
    __syncthreads();
    if (!tid) g_mode = sf ? 2 : (sg ? 1 : 0);
}

// ---------------- attention: full fp16, 1 sample/CTA, 3 CTAs/SM --------------
#define XH_OFF   0        /* x fp16: 64 x 512 */
#define STG_OFF  32768    /* Mt16 chunk: 64 x 512 */
#define TSH_OFF  65536    /* ts fp16: 64 x 128 */
#define SMEM_SZ  73728
#define SC_OFF   STG_OFF           /* f32 [64][68] after GEMMs */
#define DF_OFF   TSH_OFF           /* 64 f */
#define WGT_OFF  (TSH_OFF + 256)   /* 64 f */
#define XW_OFF   (TSH_OFF + 512)   /* 256 f */
#define XWP_OFF  (TSH_OFF + 2048)  /* 512 f partials */
#define XGP_OFF  (TSH_OFF + 4096)  /* 256 f partials */

__global__ void __launch_bounds__(256, 3) attn_mma(const float* __restrict__ x,
                                                   const void* __restrict__ mask) {
    extern __shared__ char smem[];
    const uint32_t sb = smem_u32(smem);
    const int tid = threadIdx.x, lane = tid & 31, w = tid >> 5;
    const int n = blockIdx.x;

    // stage chunk 0 of Mt16
    for (int u = tid; u < 2048; u += 256) {
        int row = u >> 5, c16 = (u & 31) << 4;
        uint32_t d = STG_OFF + row * 512 + (c16 ^ ((row & 7) << 4));
        cp16(sb + d, (const uint4*)g_Mt16 + u);
    }
    CP_COMMIT();

    // load x f32 -> fp16 smem (swizzled)
    const float2* xb = (const float2*)(x + (size_t)n * (L_TOK * E_DIM));
    for (int idx = tid; idx < 8192; idx += 256) {
        int r = idx >> 7, cp = idx & 127;
        float2 v = xb[idx];
        uint32_t boff = (uint32_t)(r * 512 + ((cp * 4) ^ ((r & 7) << 4)));
        *(uint32_t*)(smem + XH_OFF + boff) =
            pack_h2(__float2half_rn(v.x), __float2half_rn(v.y));
    }
    CP_WAIT0();
    __syncthreads();

    // warp layout: 4x2 grid of m16n32 tiles over 64x64 outputs
    const int mg = w >> 1, ng = w & 1;
    const int arow = mg * 16 + (lane & 15);
    const uint32_t a_rot = (arow & 7) << 4, a_klo = (lane >> 4) << 4;
    const uint32_t axh = sb + XH_OFF + arow * 512;
    const uint32_t ath = sb + TSH_OFF + arow * 128;
    const int br0 = ng * 32 + (lane & 7) + ((lane & 16) >> 1), br1 = br0 + 16;
    const uint32_t b_rot0 = (br0 & 7) << 4, b_rot1 = (br1 & 7) << 4;
    const uint32_t bklo = ((lane >> 3) & 1) << 4;

    float acc2[4][4];
#pragma unroll
    for (int nt = 0; nt < 4; nt++)
#pragma unroll
        for (int q = 0; q < 4; q++) acc2[nt][q] = 0.f;

    for (int ch = 0; ch < 4; ch++) {
        // GEMM1: ts_ch = x @ Mt16_ch^T  (K=256)
        float acc1[4][4];
#pragma unroll
        for (int nt = 0; nt < 4; nt++)
#pragma unroll
            for (int q = 0; q < 4; q++) acc1[nt][q] = 0.f;
        const uint32_t sg0 = sb + STG_OFF + br0 * 512, sg1 = sb + STG_OFF + br1 * 512;
#pragma unroll 4
        for (int ks = 0; ks < 16; ks++) {
            uint32_t kb = ks * 32;
            uint32_t Ah[4], B0[4], B1[4];
            ldm4(Ah, axh + ((kb + a_klo) ^ a_rot));
            ldm4(B0, sg0 + ((kb + bklo) ^ b_rot0));
            ldm4(B1, sg1 + ((kb + bklo) ^ b_rot1));
            mma_fp16(acc1[0], Ah, B0); mma_fp16(acc1[1], Ah, B0 + 2);
            mma_fp16(acc1[2], Ah, B1); mma_fp16(acc1[3], Ah, B1 + 2);
        }
        // write ts chunk (fp16, swizzled 128B rows)
#pragma unroll
        for (int nt = 0; nt < 4; nt++) {
            int col = ng * 32 + nt * 8 + 2 * (lane & 3);
            int r0 = mg * 16 + (lane >> 2);
#pragma unroll
            for (int hh = 0; hh < 2; hh++) {
                int rr = r0 + 8 * hh;
                uint32_t boff = (uint32_t)(rr * 128 + ((col * 2) ^ ((rr & 7) << 4)));
                *(uint32_t*)(smem + TSH_OFF + boff) =
                    pack_h2(__float2half_rn(acc1[nt][2 * hh]),
                            __float2half_rn(acc1[nt][2 * hh + 1]));
            }
        }
        __syncthreads();   // ts visible; GEMM1 done reading STG

        // prefetch next Mt16 chunk (overlaps GEMM2)
        if (ch < 3) {
            for (int u = tid; u < 2048; u += 256) {
                int row = u >> 5, c16 = (u & 31) << 4;
                uint32_t d = STG_OFF + row * 512 + (c16 ^ ((row & 7) << 4));
                cp16(sb + d, (const uint4*)(g_Mt16 + (ch + 1) * 16384) + u);
            }
            CP_COMMIT();
        }

        // GEMM2 partial: sc += ts_ch @ x_ch^T  (K=64)
        const uint32_t bxh0 = sb + XH_OFF + br0 * 512, bxh1 = sb + XH_OFF + br1 * 512;
#pragma unroll
        for (int ks = 0; ks < 4; ks++) {
            uint32_t kb = ks * 32, xc = ch * 128 + kb + bklo;
            uint32_t Ah[4], Bh0[4], Bh1[4];
            ldm4(Ah, ath + ((kb + a_klo) ^ a_rot));
            ldm4(Bh0, bxh0 + (xc ^ b_rot0));
            ldm4(Bh1, bxh1 + (xc ^ b_rot1));
            mma_fp16(acc2[0], Ah, Bh0); mma_fp16(acc2[1], Ah, Bh0 + 2);
            mma_fp16(acc2[2], Ah, Bh1); mma_fp16(acc2[3], Ah, Bh1 + 2);
        }
        if (ch < 3) { CP_WAIT0(); }
        __syncthreads();
    }

    // ---- write sc (overlay STG), scaled ----
    float* scp = (float*)(smem + SC_OFF);
#pragma unroll
    for (int nt = 0; nt < 4; nt++) {
        int col = ng * 32 + nt * 8 + 2 * (lane & 3);
        int r0 = mg * 16 + (lane >> 2);
        scp[r0 * 68 + col]           = acc2[nt][0] * 0.0625f;
        scp[r0 * 68 + col + 1]       = acc2[nt][1] * 0.0625f;
        scp[(r0 + 8) * 68 + col]     = acc2[nt][2] * 0.0625f;
        scp[(r0 + 8) * 68 + col + 1] = acc2[nt][3] * 0.0625f;
    }

    // ---- dropped flags + wgt init (mode precomputed in prep2) ----
    float* dfp = (float*)(smem + DF_OFF);
    float* wgt = (float*)(smem + WGT_OFF);
    float* xw  = (float*)(smem + XW_OFF);
    float* xwp = (float*)(smem + XWP_OFF);
    float* xgp = (float*)(smem + XGP_OFF);
    if (tid < 64) {
        int mode = g_mode;
        size_t mi = (size_t)n * 64 + tid;
        bool at;
        if (mode == 0)      at = ((const int*)mask)[mi] != 0;
        else if (mode == 1) at = ((const uint8_t*)mask)[mi] != 0;
        else                at = ((const float*)mask)[mi] != 0.f;
        dfp[tid] = at ? 0.f : 1.f;
        wgt[tid] = 0.f;
    }
    __syncthreads();

    // ---- softmax: 8 rows/warp ----
    {
        const bool dk0 = dfp[lane] > 0.5f, dk1 = dfp[lane + 32] > 0.5f;
        float wa0 = 0.f, wa1 = 0.f;
#pragma unroll
        for (int r = 0; r < 8; r++) {
            int lq = w * 8 + r;
            bool dq = dfp[lq] > 0.5f;
            float s0 = scp[lq * 68 + lane], s1 = scp[lq * 68 + lane + 32];
            if (dq && dk0) s0 = -1e30f;
            if (dq && dk1) s1 = -1e30f;
            float m = fmaxf(s0, s1);
#pragma unroll
            for (int o = 16; o; o >>= 1) m = fmaxf(m, __shfl_xor_sync(0xffffffffu, m, o));
            float e0 = __expf(s0 - m), e1 = __expf(s1 - m);
            float ss = e0 + e1;
#pragma unroll
            for (int o = 16; o; o >>= 1) ss += __shfl_xor_sync(0xffffffffu, ss, o);
            float inv = 1.f / ss;
            wa0 += e0 * inv;
            wa1 += e1 * inv;
        }
        atomicAdd(&wgt[lane], wa0);
        atomicAdd(&wgt[lane + 32], wa1);
    }
    __syncthreads();

    // ---- xw partial: thread t -> col pair c=(t&127), k-half kh=(t>>7) ----
    {
        const int c = tid & 127, kh = tid >> 7;
        float a0 = 0.f, a1 = 0.f;
#pragma unroll 8
        for (int kk = 0; kk < 32; kk++) {
            int k = kh * 32 + kk;
            uint32_t boff = (uint32_t)(k * 512 + ((4 * c) ^ ((k & 7) << 4)));
            __half2 hv = *(__half2*)(smem + XH_OFF + boff);
            float2 fv = __half22float2(hv);
            float wk = wgt[k];
            a0 += wk * fv.x;
            a1 += wk * fv.y;
        }
        xwp[kh * 256 + 2 * c]     = a0;
        xwp[kh * 256 + 2 * c + 1] = a1;
    }
    __syncthreads();
    xw[tid] = xwp[tid] + xwp[256 + tid];
    __syncthreads();

    // ---- xg partial: g=(tid&127), j-half jh=(tid>>7), 4-way unrolled ----
    {
        const int g = tid & 127, jh = tid >> 7;
        const float* Wp = g_W2 + (size_t)jh * 128 * 128 + g;
        const float* xwp2 = xw + jh * 128;
        float a0 = 0.f, a1 = 0.f, a2 = 0.f, a3 = 0.f;
#pragma unroll 8
        for (int j = 0; j < 128; j += 4) {
            a0 += xwp2[j]     * __ldg(Wp + (size_t)j * 128);
            a1 += xwp2[j + 1] * __ldg(Wp + (size_t)(j + 1) * 128);
            a2 += xwp2[j + 2] * __ldg(Wp + (size_t)(j + 2) * 128);
            a3 += xwp2[j + 3] * __ldg(Wp + (size_t)(j + 3) * 128);
        }
        xgp[jh * 128 + g] = (a0 + a1) + (a2 + a3);
    }
    __syncthreads();
    if (tid < 128)
        g_xg[(size_t)n * 128 + tid] = g_bias[tid] + xgp[tid] + xgp[128 + tid];
}

// ---------------- LSTM scan + critic: float4 weights, pipelined --------------
__device__ __forceinline__ float sigmoidf_(float v) { return 1.f / (1.f + __expf(-v)); }

__global__ void __launch_bounds__(128) lstm_kernel(const float* __restrict__ done,
                                                   const float* __restrict__ h0,
                                                   const float* __restrict__ c0,
                                                   const float* __restrict__ whh,
                                                   const float* __restrict__ cw,
                                                   const float* __restrict__ cb,
                                                   float* __restrict__ out) {
    __shared__ float4 whs4[1024];   // [m*32+lane] = (w_i, w_f, w_g, w_o)
    const int tid = threadIdx.x, lane = tid & 31, w = tid >> 5;
    const int b = blockIdx.x * 4 + w;
    for (int e = tid; e < 1024; e += 128) {
        int m = e >> 5, ln = e & 31;
        whs4[e] = make_float4(whh[ln * 32 + m],
                              whh[(32 + ln) * 32 + m],
                              whh[(64 + ln) * 32 + m],
                              whh[(96 + ln) * 32 + m]);
    }
    __syncthreads();
    float h = h0[b * H_DIM + lane], c = c0[b * H_DIM + lane];
    const float cwv = cw[lane], cbv = cb[0];

    float dn = done[b];
    const float* xp = g_xg + (size_t)b * 128;
    float pai = xp[lane], paf = xp[32 + lane], pag = xp[64 + lane], pao = xp[96 + lane];

    for (int t = 0; t < T_STEPS; t++) {
        float ai = pai, af = paf, ag = pag, ao = pao, dc = dn;
        if (t < 63) {
            int n2 = (t + 1) * B_ENV + b;
            dn = done[n2];
            const float* x2 = g_xg + (size_t)n2 * 128;
            pai = x2[lane]; paf = x2[32 + lane]; pag = x2[64 + lane]; pao = x2[96 + lane];
        }
        float keep = 1.f - dc;
        h *= keep; c *= keep;
        float hv[32];
#pragma unroll
        for (int m = 0; m < 32; m++) hv[m] = __shfl_sync(0xffffffffu, h, m);
#pragma unroll
        for (int m = 0; m < 32; m++) {
            float4 wv = whs4[m * 32 + lane];
            ai += hv[m] * wv.x;
            af += hv[m] * wv.y;
            ag += hv[m] * wv.z;
            ao += hv[m] * wv.w;
        }
        float gi = sigmoidf_(ai), gf = sigmoidf_(af), gg = tanhf(ag), go = sigmoidf_(ao);
        c = gf * c + gi * gg;
        h = go * tanhf(c);
        float pv = h * cwv;
#pragma unroll
        for (int o = 16; o; o >>= 1) pv += __shfl_xor_sync(0xffffffffu, pv, o);
        if (lane == 0) out[t * B_ENV + b] = pv + cbv;
    }
}

extern "C" void kernel_launch(void* const* d_in, const int* in_sizes, int n_in,
                              void* d_out, int out_size) {
    const float* x    = (const float*)d_in[0];
    const float* done = (const float*)d_in[1];
    const void*  mask = d_in[2];
    const float* h0   = (const float*)d_in[3];
    const float* c0   = (const float*)d_in[4];
    const float* ipw  = (const float*)d_in[5];
    const float* opw  = (const float*)d_in[6];
    const float* wih  = (const float*)d_in[7];
    const float* whh  = (const float*)d_in[8];
    const float* bih  = (const float*)d_in[9];
    const float* bhh  = (const float*)d_in[10];
    const float* cw   = (const float*)d_in[11];
    const float* cb   = (const float*)d_in[12];
    float*       out  = (float*)d_out;
    (void)in_sizes; (void)n_in; (void)out_size;

    cudaFuncSetAttribute(attn_mma, cudaFuncAttributeMaxDynamicSharedMemorySize, SMEM_SZ);
    prep1<<<128, 256>>>(ipw, opw);
    prep2<<<97, 256>>>(wih, bih, bhh, mask);
    attn_mma<<<N_TOT, 256, SMEM_SZ>>>(x, mask);
    lstm_kernel<<<32, 128>>>(done, h0, c0, whh, cw, cb, out);
}

// round 15
// speedup vs baseline: 2.8843x; 1.0993x over previous
#include <cuda_runtime.h>
#include <cuda_fp16.h>
#include <cstdint>

#define T_STEPS 64
#define B_ENV 128
#define L_TOK 64
#define E_DIM 256
#define H_DIM 32
#define N_TOT (T_STEPS * B_ENV)

__device__ float g_M[65536];
__device__ float g_WeffT[65536];
__device__ float g_W2[32768];
__device__ float g_bias[128];
__device__ unsigned short g_Mt16[65536]; // fp16 of M^T [j][i]
__device__ float g_xw[(size_t)N_TOT * 256]; // attention-pooled features
__device__ float g_xg[(size_t)N_TOT * 128];
__device__ int g_mode;

// ---------------- helpers ----------------
__device__ __forceinline__ uint32_t smem_u32(const void* p) {
    uint32_t a;
    asm("{ .reg .u64 t; cvta.to.shared.u64 t, %1; cvt.u32.u64 %0, t; }" : "=r"(a) : "l"(p));
    return a;
}
__device__ __forceinline__ void ldm4(uint32_t* r, uint32_t a) {
    asm volatile("ldmatrix.sync.aligned.m8n8.x4.shared.b16 {%0,%1,%2,%3}, [%4];"
        : "=r"(r[0]), "=r"(r[1]), "=r"(r[2]), "=r"(r[3]) : "r"(a));
}
__device__ __forceinline__ void mma_fp16(float* d, const uint32_t* a, const uint32_t* b) {
    asm volatile("mma.sync.aligned.m16n8k16.row.col.f32.f16.f16.f32 "
        "{%0,%1,%2,%3}, {%4,%5,%6,%7}, {%8,%9}, {%0,%1,%2,%3};"
        : "+f"(d[0]), "+f"(d[1]), "+f"(d[2]), "+f"(d[3])
        : "r"(a[0]), "r"(a[1]), "r"(a[2]), "r"(a[3]), "r"(b[0]), "r"(b[1]));
}
__device__ __forceinline__ uint32_t pack_h2(__half lo, __half hi) {
    __half2 p = __halves2half2(lo, hi);
    return *(uint32_t*)&p;
}
__device__ __forceinline__ void cp16(uint32_t dst, const void* src) {
    asm volatile("cp.async.cg.shared.global [%0], [%1], 16;" :: "r"(dst), "l"(src));
}
#define CP_COMMIT() asm volatile("cp.async.commit_group;" ::: "memory")
#define CP_WAIT0()  asm volatile("cp.async.wait_group 0;" ::: "memory")

// ---------------- prep1: M (b<64), WeffT (b>=64) ----------------
__global__ void __launch_bounds__(256) prep1(const float* __restrict__ ipw, const float* __restrict__ opw) {
    __shared__ float As[32][33], Bs[32][33];
    const int b = blockIdx.x, tid = threadIdx.x, tx = tid & 31, ty = tid >> 5;
    float acc[4] = {0.f, 0.f, 0.f, 0.f};
    if (b < 64) {
        int i0 = (b >> 3) * 32, j0 = (b & 7) * 32;
        const float *Wq = ipw, *Wk = ipw + 65536;
        for (int e0 = 0; e0 < 256; e0 += 32) {
#pragma unroll
            for (int r = 0; r < 4; r++) {
                int e = ty + 8 * r;
                As[e][tx] = Wq[(e0 + e) * 256 + i0 + tx];
                Bs[e][tx] = Wk[(e0 + e) * 256 + j0 + tx];
            }
            __syncthreads();
#pragma unroll 8
            for (int e = 0; e < 32; e++) {
                float bv = Bs[e][tx];
#pragma unroll
                for (int r = 0; r < 4; r++) acc[r] += As[e][ty + 8 * r] * bv;
            }
            __syncthreads();
        }
#pragma unroll
        for (int r = 0; r < 4; r++) g_M[(i0 + ty + 8 * r) * 256 + j0 + tx] = acc[r];
    } else {
        int t = b - 64, j0 = (t >> 3) * 32, f0 = (t & 7) * 32;
        const float* Wv = ipw + 131072;
        for (int e0 = 0; e0 < 256; e0 += 32) {
#pragma unroll
            for (int r = 0; r < 4; r++) {
                int e = ty + 8 * r;
                As[e][tx] = Wv[(e0 + e) * 256 + j0 + tx];
                Bs[tx][e] = opw[(f0 + e) * 256 + e0 + tx];
            }
            __syncthreads();
#pragma unroll 8
            for (int e = 0; e < 32; e++) {
                float bv = Bs[e][tx];
#pragma unroll
                for (int r = 0; r < 4; r++) acc[r] += As[e][ty + 8 * r] * bv;
            }
            __syncthreads();
        }
#pragma unroll
        for (int r = 0; r < 4; r++) g_WeffT[(j0 + ty + 8 * r) * 256 + f0 + tx] = acc[r];
    }
}

// ------- prep2: Mt fp16 (b<64), W2 (64..95), bias + mask-mode (96) -------
__global__ void __launch_bounds__(256) prep2(const float* __restrict__ wih,
                                             const float* __restrict__ bih,
                                             const float* __restrict__ bhh,
                                             const void* __restrict__ mask) {
    __shared__ float As[32][33], Bs[32][33];
    const int b = blockIdx.x, tid = threadIdx.x, tx = tid & 31, ty = tid >> 5;
    if (b < 64) {
        int i0 = (b >> 3) * 32, j0 = (b & 7) * 32;
#pragma unroll
        for (int r = 0; r < 4; r++) As[ty + 8 * r][tx] = g_M[(i0 + ty + 8 * r) * 256 + j0 + tx];
        __syncthreads();
#pragma unroll
        for (int r = 0; r < 4; r++) {
            int jj = ty + 8 * r;
            __half h = __float2half_rn(As[tx][jj]);
            g_Mt16[(j0 + jj) * 256 + i0 + tx] = *(unsigned short*)&h;
        }
        return;
    }
    if (b < 96) {
        int t = b - 64, j0 = (t >> 2) * 32, g0 = (t & 3) * 32;
        float acc[4] = {0.f, 0.f, 0.f, 0.f};
        for (int f0 = 0; f0 < 256; f0 += 32) {
#pragma unroll
            for (int r = 0; r < 4; r++) {
                int e = ty + 8 * r;
                As[tx][e] = g_WeffT[(j0 + e) * 256 + f0 + tx];
                Bs[tx][e] = wih[(g0 + e) * 256 + f0 + tx];
            }
            __syncthreads();
#pragma unroll 8
            for (int f = 0; f < 32; f++) {
                float bv = Bs[f][tx];
#pragma unroll
                for (int r = 0; r < 4; r++) acc[r] += As[f][ty + 8 * r] * bv;
            }
            __syncthreads();
        }
#pragma unroll
        for (int r = 0; r < 4; r++) g_W2[(j0 + ty + 8 * r) * 128 + g0 + tx] = acc[r];
        return;
    }
    if (tid < 128) g_bias[tid] = bih[tid] + bhh[tid];
    __shared__ int sf, sg;
    if (!tid) { sf = 0; sg = 0; }
    __syncthreads();
    const unsigned* mw = (const unsigned*)mask;
    int f = 0, g = 0;
    for (int i = tid; i < 4096; i += 256) {
        unsigned v = mw[i];
        if (v == 0x3F800000u) f = 1;
        if (v > 1u) g = 1;
    }
    if (f) atomicOr(&sf, 1);
    if (g) atomicOr(&sg, 1);
    __syncthreads();
    if (!tid) g_mode = sf ? 2 : (sg ? 1 : 0);
}

// ---------------- attention: full fp16, 1 sample/CTA, 3 CTAs/SM --------------
#define XH_OFF   0        /* x fp16: 64 x 512 */
#define STG_OFF  32768    /* Mt16 chunk: 64 x 512 */
#define TSH_OFF  65536    /* ts fp16: 64 x 128 */
#define SMEM_SZ  73728
#define SC_OFF   STG_OFF           /* f32 [64][68] after GEMMs */
#define DF_OFF   TSH_OFF           /* 64 f */
#define WGT_OFF  (TSH_OFF + 256)   /* 64 f */
#define XWP_OFF  (TSH_OFF + 2048)  /* 512 f partials */

__global__ void __launch_bounds__(256, 3) attn_mma(const float* __restrict__ x,
                                                   const void* __restrict__ mask) {
    extern __shared__ char smem[];
    const uint32_t sb = smem_u32(smem);
    const int tid = threadIdx.x, lane = tid & 31, w = tid >> 5;
    const int n = blockIdx.x;

    // stage chunk 0 of Mt16
    for (int u = tid; u < 2048; u += 256) {
        int row = u >> 5, c16 = (u & 31) << 4;
        uint32_t d = STG_OFF + row * 512 + (c16 ^ ((row & 7) << 4));
        cp16(sb + d, (const uint4*)g_Mt16 + u);
    }
    CP_COMMIT();

    // load x f32 -> fp16 smem (swizzled)
    const float2* xb = (const float2*)(x + (size_t)n * (L_TOK * E_DIM));
    for (int idx = tid; idx < 8192; idx += 256) {
        int r = idx >> 7, cp = idx & 127;
        float2 v = xb[idx];
        uint32_t boff = (uint32_t)(r * 512 + ((cp * 4) ^ ((r & 7) << 4)));
        *(uint32_t*)(smem + XH_OFF + boff) =
            pack_h2(__float2half_rn(v.x), __float2half_rn(v.y));
    }
    CP_WAIT0();
    __syncthreads();

    const int mg = w >> 1, ng = w & 1;
    const int arow = mg * 16 + (lane & 15);
    const uint32_t a_rot = (arow & 7) << 4, a_klo = (lane >> 4) << 4;
    const uint32_t axh = sb + XH_OFF + arow * 512;
    const uint32_t ath = sb + TSH_OFF + arow * 128;
    const int br0 = ng * 32 + (lane & 7) + ((lane & 16) >> 1), br1 = br0 + 16;
    const uint32_t b_rot0 = (br0 & 7) << 4, b_rot1 = (br1 & 7) << 4;
    const uint32_t bklo = ((lane >> 3) & 1) << 4;

    float acc2[4][4];
#pragma unroll
    for (int nt = 0; nt < 4; nt++)
#pragma unroll
        for (int q = 0; q < 4; q++) acc2[nt][q] = 0.f;

    for (int ch = 0; ch < 4; ch++) {
        float acc1[4][4];
#pragma unroll
        for (int nt = 0; nt < 4; nt++)
#pragma unroll
            for (int q = 0; q < 4; q++) acc1[nt][q] = 0.f;
        const uint32_t sg0 = sb + STG_OFF + br0 * 512, sg1 = sb + STG_OFF + br1 * 512;
#pragma unroll 4
        for (int ks = 0; ks < 16; ks++) {
            uint32_t kb = ks * 32;
            uint32_t Ah[4], B0[4], B1[4];
            ldm4(Ah, axh + ((kb + a_klo) ^ a_rot));
            ldm4(B0, sg0 + ((kb + bklo) ^ b_rot0));
            ldm4(B1, sg1 + ((kb + bklo) ^ b_rot1));
            mma_fp16(acc1[0], Ah, B0); mma_fp16(acc1[1], Ah, B0 + 2);
            mma_fp16(acc1[2], Ah, B1); mma_fp16(acc1[3], Ah, B1 + 2);
        }
#pragma unroll
        for (int nt = 0; nt < 4; nt++) {
            int col = ng * 32 + nt * 8 + 2 * (lane & 3);
            int r0 = mg * 16 + (lane >> 2);
#pragma unroll
            for (int hh = 0; hh < 2; hh++) {
                int rr = r0 + 8 * hh;
                uint32_t boff = (uint32_t)(rr * 128 + ((col * 2) ^ ((rr & 7) << 4)));
                *(uint32_t*)(smem + TSH_OFF + boff) =
                    pack_h2(__float2half_rn(acc1[nt][2 * hh]),
                            __float2half_rn(acc1[nt][2 * hh + 1]));
            }
        }
        __syncthreads();

        if (ch < 3) {
            for (int u = tid; u < 2048; u += 256) {
                int row = u >> 5, c16 = (u & 31) << 4;
                uint32_t d = STG_OFF + row * 512 + (c16 ^ ((row & 7) << 4));
                cp16(sb + d, (const uint4*)(g_Mt16 + (ch + 1) * 16384) + u);
            }
            CP_COMMIT();
        }

        const uint32_t bxh0 = sb + XH_OFF + br0 * 512, bxh1 = sb + XH_OFF + br1 * 512;
#pragma unroll
        for (int ks = 0; ks < 4; ks++) {
            uint32_t kb = ks * 32, xc = ch * 128 + kb + bklo;
            uint32_t Ah[4], Bh0[4], Bh1[4];
            ldm4(Ah, ath + ((kb + a_klo) ^ a_rot));
            ldm4(Bh0, bxh0 + (xc ^ b_rot0));
            ldm4(Bh1, bxh1 + (xc ^ b_rot1));
            mma_fp16(acc2[0], Ah, Bh0); mma_fp16(acc2[1], Ah, Bh0 + 2);
            mma_fp16(acc2[2], Ah, Bh1); mma_fp16(acc2[3], Ah, Bh1 + 2);
        }
        if (ch < 3) { CP_WAIT0(); }
        __syncthreads();
    }

    // ---- write sc (overlay STG), scaled ----
    float* scp = (float*)(smem + SC_OFF);
#pragma unroll
    for (int nt = 0; nt < 4; nt++) {
        int col = ng * 32 + nt * 8 + 2 * (lane & 3);
        int r0 = mg * 16 + (lane >> 2);
        scp[r0 * 68 + col]           = acc2[nt][0] * 0.0625f;
        scp[r0 * 68 + col + 1]       = acc2[nt][1] * 0.0625f;
        scp[(r0 + 8) * 68 + col]     = acc2[nt][2] * 0.0625f;
        scp[(r0 + 8) * 68 + col + 1] = acc2[nt][3] * 0.0625f;
    }

    float* dfp = (float*)(smem + DF_OFF);
    float* wgt = (float*)(smem + WGT_OFF);
    float* xwp = (float*)(smem + XWP_OFF);
    if (tid < 64) {
        int mode = g_mode;
        size_t mi = (size_t)n * 64 + tid;
        bool at;
        if (mode == 0)      at = ((const int*)mask)[mi] != 0;
        else if (mode == 1) at = ((const uint8_t*)mask)[mi] != 0;
        else                at = ((const float*)mask)[mi] != 0.f;
        dfp[tid] = at ? 0.f : 1.f;
        wgt[tid] = 0.f;
    }
    __syncthreads();

    // ---- softmax: 8 rows/warp ----
    {
        const bool dk0 = dfp[lane] > 0.5f, dk1 = dfp[lane + 32] > 0.5f;
        float wa0 = 0.f, wa1 = 0.f;
#pragma unroll
        for (int r = 0; r < 8; r++) {
            int lq = w * 8 + r;
            bool dq = dfp[lq] > 0.5f;
            float s0 = scp[lq * 68 + lane], s1 = scp[lq * 68 + lane + 32];
            if (dq && dk0) s0 = -1e30f;
            if (dq && dk1) s1 = -1e30f;
            float m = fmaxf(s0, s1);
#pragma unroll
            for (int o = 16; o; o >>= 1) m = fmaxf(m, __shfl_xor_sync(0xffffffffu, m, o));
            float e0 = __expf(s0 - m), e1 = __expf(s1 - m);
            float ss = e0 + e1;
#pragma unroll
            for (int o = 16; o; o >>= 1) ss += __shfl_xor_sync(0xffffffffu, ss, o);
            float inv = 1.f / ss;
            wa0 += e0 * inv;
            wa1 += e1 * inv;
        }
        atomicAdd(&wgt[lane], wa0);
        atomicAdd(&wgt[lane + 32], wa1);
    }
    __syncthreads();

    // ---- xw partials -> global g_xw ----
    {
        const int c = tid & 127, kh = tid >> 7;
        float a0 = 0.f, a1 = 0.f;
#pragma unroll 8
        for (int kk = 0; kk < 32; kk++) {
            int k = kh * 32 + kk;
            uint32_t boff = (uint32_t)(k * 512 + ((4 * c) ^ ((k & 7) << 4)));
            __half2 hv = *(__half2*)(smem + XH_OFF + boff);
            float2 fv = __half22float2(hv);
            float wk = wgt[k];
            a0 += wk * fv.x;
            a1 += wk * fv.y;
        }
        xwp[kh * 256 + 2 * c]     = a0;
        xwp[kh * 256 + 2 * c + 1] = a1;
    }
    __syncthreads();
    g_xw[(size_t)n * 256 + tid] = xwp[tid] + xwp[256 + tid];
}

// -------- xg_gemm: g_xg = g_xw @ W2 + bias  (256 CTAs x 32 samples) ---------
__global__ void __launch_bounds__(256) xg_gemm() {
    __shared__ float As[32][36];    // [j][sample]
    __shared__ float Bs[32][132];   // [j][gate]
    const int tid = threadIdx.x;
    const int n0 = blockIdx.x * 32;
    const int sgrp = tid >> 5, ggrp = tid & 31;
    float acc[4][4];
#pragma unroll
    for (int si = 0; si < 4; si++)
#pragma unroll
        for (int gi = 0; gi < 4; gi++) acc[si][gi] = 0.f;

    for (int e0 = 0; e0 < 256; e0 += 32) {
        for (int l = tid; l < 1024; l += 256) {
            int ss = l >> 5, jj = l & 31;
            As[jj][ss] = g_xw[(size_t)(n0 + ss) * 256 + e0 + jj];
        }
        for (int l = tid; l < 4096; l += 256) {
            int jj = l >> 7, g = l & 127;
            Bs[jj][g] = g_W2[(e0 + jj) * 128 + g];
        }
        __syncthreads();
#pragma unroll 8
        for (int jj = 0; jj < 32; jj++) {
            float4 av = *(float4*)&As[jj][sgrp * 4];
            float4 bv = *(float4*)&Bs[jj][ggrp * 4];
            float a[4] = {av.x, av.y, av.z, av.w};
            float bb[4] = {bv.x, bv.y, bv.z, bv.w};
#pragma unroll
            for (int si = 0; si < 4; si++)
#pragma unroll
                for (int gi = 0; gi < 4; gi++) acc[si][gi] += a[si] * bb[gi];
        }
        __syncthreads();
    }
#pragma unroll
    for (int si = 0; si < 4; si++)
#pragma unroll
        for (int gi = 0; gi < 4; gi++) {
            int g = ggrp * 4 + gi;
            g_xg[(size_t)(n0 + sgrp * 4 + si) * 128 + g] = acc[si][gi] + g_bias[g];
        }
}

// ------- LSTM scan: critic hoisted out of the loop; 64 blocks x 2 warps ------
__device__ __forceinline__ float sigmoidf_(float v) { return 1.f / (1.f + __expf(-v)); }

__global__ void __launch_bounds__(64) lstm_kernel(const float* __restrict__ done,
                                                  const float* __restrict__ h0,
                                                  const float* __restrict__ c0,
                                                  const float* __restrict__ whh,
                                                  const float* __restrict__ cw,
                                                  const float* __restrict__ cb,
                                                  float* __restrict__ out) {
    __shared__ float4 whs4[1024];   // [m*32+lane] = (w_i, w_f, w_g, w_o)
    __shared__ float hs[2][64][33]; // [warp][t][lane]
    __shared__ float cws[32];
    const int tid = threadIdx.x, lane = tid & 31, w = tid >> 5;
    const int b = blockIdx.x * 2 + w;
    for (int e = tid; e < 1024; e += 64) {
        int m = e >> 5, ln = e & 31;
        whs4[e] = make_float4(whh[ln * 32 + m],
                              whh[(32 + ln) * 32 + m],
                              whh[(64 + ln) * 32 + m],
                              whh[(96 + ln) * 32 + m]);
    }
    if (tid < 32) cws[tid] = cw[tid];
    __syncthreads();
    float h = h0[b * H_DIM + lane], c = c0[b * H_DIM + lane];

    float dn = done[b];
    const float* xp = g_xg + (size_t)b * 128;
    float pai = xp[lane], paf = xp[32 + lane], pag = xp[64 + lane], pao = xp[96 + lane];

    for (int t = 0; t < T_STEPS; t++) {
        float ai = pai, af = paf, ag = pag, ao = pao, dc = dn;
        if (t < 63) {
            int n2 = (t + 1) * B_ENV + b;
            dn = done[n2];
            const float* x2 = g_xg + (size_t)n2 * 128;
            pai = x2[lane]; paf = x2[32 + lane]; pag = x2[64 + lane]; pao = x2[96 + lane];
        }
        float keep = 1.f - dc;
        h *= keep; c *= keep;
        float hv[32];
#pragma unroll
        for (int m = 0; m < 32; m++) hv[m] = __shfl_sync(0xffffffffu, h, m);
#pragma unroll
        for (int m = 0; m < 32; m++) {
            float4 wv = whs4[m * 32 + lane];
            ai += hv[m] * wv.x;
            af += hv[m] * wv.y;
            ag += hv[m] * wv.z;
            ao += hv[m] * wv.w;
        }
        float gi = sigmoidf_(ai), gf = sigmoidf_(af), gg = tanhf(ag), go = sigmoidf_(ao);
        c = gf * c + gi * gg;
        h = go * tanhf(c);
        hs[w][t][lane] = h;
    }
    __syncwarp();
    // critic: lane handles t = lane, lane+32
    const float cbv = cb[0];
#pragma unroll
    for (int half = 0; half < 2; half++) {
        int t = lane + half * 32;
        float a = 0.f;
#pragma unroll 8
        for (int m = 0; m < 32; m++) a += hs[w][t][m] * cws[m];
        out[t * B_ENV + b] = a + cbv;
    }
}

extern "C" void kernel_launch(void* const* d_in, const int* in_sizes, int n_in,
                              void* d_out, int out_size) {
    const float* x    = (const float*)d_in[0];
    const float* done = (const float*)d_in[1];
    const void*  mask = d_in[2];
    const float* h0   = (const float*)d_in[3];
    const float* c0   = (const float*)d_in[4];
    const float* ipw  = (const float*)d_in[5];
    const float* opw  = (const float*)d_in[6];
    const float* wih  = (const float*)d_in[7];
    const float* whh  = (const float*)d_in[8];
    const float* bih  = (const float*)d_in[9];
    const float* bhh  = (const float*)d_in[10];
    const float* cw   = (const float*)d_in[11];
    const float* cb   = (const float*)d_in[12];
    float*       out  = (float*)d_out;
    (void)in_sizes; (void)n_in; (void)out_size;

    cudaFuncSetAttribute(attn_mma, cudaFuncAttributeMaxDynamicSharedMemorySize, SMEM_SZ);
    prep1<<<128, 256>>>(ipw, opw);
    prep2<<<97, 256>>>(wih, bih, bhh, mask);
    attn_mma<<<N_TOT, 256, SMEM_SZ>>>(x, mask);
    xg_gemm<<<N_TOT / 32, 256>>>();
    lstm_kernel<<<64, 64>>>(done, h0, c0, whh, cw, cb, out);
}